// round 8
// baseline (speedup 1.0000x reference)
#include <cuda_runtime.h>
#include <cuda_bf16.h>
#include <cstdint>

#define D 128
#define MAXN 50176
#define MAXE 640000

typedef unsigned long long u64;

// ---------------------------------------------------------------------------
// Scratch (no cudaMalloc allowed).
// ---------------------------------------------------------------------------
__device__ float         g_bufY[(size_t)MAXN * D];   // S_u = v2u(X_v)
__device__ float         g_bufZ[(size_t)MAXN * D];   // T_v = u2v(S_u)
__device__ float         g_P[D * D];                 // W1@W2
__device__ __nv_bfloat16 g_wthi[D * D];              // (W0@W1@W2)^T split
__device__ __nv_bfloat16 g_wtlo[D * D];
__device__ float         g_g1[D];                    // b0@W1@W2
__device__ float         g_g2[D];                    // b1@W2
__device__ float         g_du[MAXN];
__device__ float         g_dv[MAXN];
__device__ float         g_ev[MAXN];                 // u2v(d_u)
__device__ float         g_c1[MAXN];                 // v2u(e_v)
__device__ float         g_c2[MAXN];                 // v2u(d_v)

// CSR structures.
__device__ int g_rowptr_u[MAXN + 1];
__device__ int g_rowptr_v[MAXN + 1];
__device__ int g_off_u[MAXN];
__device__ int g_off_v[MAXN];
__device__ int g_srcs_u[MAXE];
__device__ int g_srcs_v[MAXE];
__device__ int g_bsum_u[64];
__device__ int g_bsum_v[64];

// ---------------------------------------------------------------------------
// mma.sync / ldmatrix helpers (baseline PTX, works on compute_103)
// ---------------------------------------------------------------------------
__device__ __forceinline__ uint32_t smem_u32(const void* p) {
    uint32_t a;
    asm("{ .reg .u64 t; cvta.to.shared.u64 t, %1; cvt.u32.u64 %0, t; }" : "=r"(a) : "l"(p));
    return a;
}

__device__ __forceinline__ void ldm_x4(uint32_t (&r)[4], uint32_t addr) {
    asm volatile("ldmatrix.sync.aligned.m8n8.x4.shared.b16 {%0,%1,%2,%3}, [%4];"
                 : "=r"(r[0]), "=r"(r[1]), "=r"(r[2]), "=r"(r[3]) : "r"(addr));
}

__device__ __forceinline__ void mma_bf16(float (&c)[4], const uint32_t (&a)[4],
                                         uint32_t b0, uint32_t b1) {
    asm volatile(
        "mma.sync.aligned.m16n8k16.row.col.f32.bf16.bf16.f32 "
        "{%0,%1,%2,%3}, {%4,%5,%6,%7}, {%8,%9}, {%0,%1,%2,%3};"
        : "+f"(c[0]), "+f"(c[1]), "+f"(c[2]), "+f"(c[3])
        : "r"(a[0]), "r"(a[1]), "r"(a[2]), "r"(a[3]), "r"(b0), "r"(b1));
}

__device__ __forceinline__ void bf16_split(float f, __nv_bfloat16& h, __nv_bfloat16& l) {
    h = __float2bfloat16(f);
    l = __float2bfloat16(f - __bfloat162float(h));
}

// ---------------------------------------------------------------------------
// CSR gather of one feature row (warp-wide, lane owns float4).
// ---------------------------------------------------------------------------
__device__ __forceinline__ float4 csr_gather_row(const float* __restrict__ src,
                                                 const int* __restrict__ srcs,
                                                 int beg, int end, int lane)
{
    float4 acc = make_float4(0.f, 0.f, 0.f, 0.f);
    int i = beg;
    for (; i + 4 <= end; i += 4) {
        int s0 = __ldg(&srcs[i + 0]);
        int s1 = __ldg(&srcs[i + 1]);
        int s2 = __ldg(&srcs[i + 2]);
        int s3 = __ldg(&srcs[i + 3]);
        float4 a = __ldg(reinterpret_cast<const float4*>(src + (size_t)s0 * D) + lane);
        float4 b = __ldg(reinterpret_cast<const float4*>(src + (size_t)s1 * D) + lane);
        float4 c = __ldg(reinterpret_cast<const float4*>(src + (size_t)s2 * D) + lane);
        float4 e = __ldg(reinterpret_cast<const float4*>(src + (size_t)s3 * D) + lane);
        acc.x += (a.x + b.x) + (c.x + e.x);
        acc.y += (a.y + b.y) + (c.y + e.y);
        acc.z += (a.z + b.z) + (c.z + e.z);
        acc.w += (a.w + b.w) + (c.w + e.w);
    }
    for (; i < end; i++) {
        int s0 = __ldg(&srcs[i]);
        float4 a = __ldg(reinterpret_cast<const float4*>(src + (size_t)s0 * D) + lane);
        acc.x += a.x; acc.y += a.y; acc.z += a.z; acc.w += a.w;
    }
    return acc;
}

// ---------------------------------------------------------------------------
// Final fused kernel: A = v2u(T_v) gathered IN-KERNEL, split to bf16 smem,
// then out = A @ W012 + c1*g1 + c2*g2 + du*g3.
// ---------------------------------------------------------------------------
#define STR 136
#define SM_G1   0
#define SM_G2   512
#define SM_G3   1024
#define SM_AHI  1536
#define SM_ALO  (SM_AHI + 64 * 272)
#define SM_BHI  (SM_ALO + 64 * 272)
#define SM_BLO  (SM_BHI + 128 * 272)
#define SM_TOT  (SM_BLO + 128 * 272)     // 105984
#define SM_EP   1536
#define EPSTR   132

__global__ __launch_bounds__(128, 2)
void gemm_fused_kernel(const float* __restrict__ Tv,
                       const int* __restrict__ rowptr,
                       const int* __restrict__ srcs,
                       const __nv_bfloat16* __restrict__ Bhi,
                       const __nv_bfloat16* __restrict__ Blo,
                       const float* __restrict__ g1,
                       const float* __restrict__ g2,
                       const float* __restrict__ g3,
                       const float* __restrict__ c1,
                       const float* __restrict__ c2,
                       const float* __restrict__ du,
                       float* __restrict__ Y,
                       int N)
{
    extern __shared__ char smem[];
    const uint32_t sb = smem_u32(smem);
    const int tid  = threadIdx.x;
    const int lane = tid & 31;
    const int warp = tid >> 5;
    const int rowBase = blockIdx.x * 64;

    ((float*)(smem + SM_G1))[tid] = g1[tid];
    ((float*)(smem + SM_G2))[tid] = g2[tid];
    ((float*)(smem + SM_G3))[tid] = g3[tid];

    // Stage B = (W012)^T splits.
    #pragma unroll 4
    for (int i = tid; i < 128 * 16; i += 128) {
        int n = i >> 4, c = i & 15;
        uint32_t so = (uint32_t)(n * 272 + c * 16);
        *(uint4*)(smem + SM_BHI + so) = *(const uint4*)(Bhi + (size_t)n * D + c * 8);
        *(uint4*)(smem + SM_BLO + so) = *(const uint4*)(Blo + (size_t)n * D + c * 8);
    }

    // Gather A = v2u(Tv) for 16 rows per warp; split to bf16 hi/lo in smem.
    const int wr = warp * 16;
    #pragma unroll 1
    for (int rr = 0; rr < 16; rr++) {
        int r = wr + rr;
        int row = rowBase + r;
        float4 acc = make_float4(0.f, 0.f, 0.f, 0.f);
        if (row < N)
            acc = csr_gather_row(Tv, srcs, __ldg(&rowptr[row]), __ldg(&rowptr[row + 1]), lane);
        __nv_bfloat16 h0, l0, h1, l1, h2, l2, h3, l3;
        bf16_split(acc.x, h0, l0); bf16_split(acc.y, h1, l1);
        bf16_split(acc.z, h2, l2); bf16_split(acc.w, h3, l3);
        __nv_bfloat162 hA = __nv_bfloat162(h0, h1), hB = __nv_bfloat162(h2, h3);
        __nv_bfloat162 lA = __nv_bfloat162(l0, l1), lB = __nv_bfloat162(l2, l3);
        uint2 hv, lv;
        hv.x = *(uint32_t*)&hA; hv.y = *(uint32_t*)&hB;
        lv.x = *(uint32_t*)&lA; lv.y = *(uint32_t*)&lB;
        uint32_t so = (uint32_t)(r * STR + lane * 4) * 2;
        *(uint2*)(smem + SM_AHI + so) = hv;
        *(uint2*)(smem + SM_ALO + so) = lv;
    }
    __syncthreads();

    float acc[16][4];
    #pragma unroll
    for (int t = 0; t < 16; t++) {
        acc[t][0] = 0.f; acc[t][1] = 0.f; acc[t][2] = 0.f; acc[t][3] = 0.f;
    }

    const uint32_t aRowOff = (uint32_t)((wr + (lane & 15)) * STR + ((lane >> 4) << 3)) * 2;
    const int nOff  = (lane & 7) + ((lane >> 4) & 1) * 8;
    const int kHalf = ((lane >> 3) & 1) * 8;
    const uint32_t bRowOff = (uint32_t)(nOff * STR + kHalf) * 2;

    #pragma unroll 1
    for (int pass = 0; pass < 3; pass++) {
        uint32_t aBase = sb + ((pass == 2) ? SM_ALO : SM_AHI) + aRowOff;
        uint32_t bBase = sb + ((pass == 1) ? SM_BLO : SM_BHI) + bRowOff;
        #pragma unroll 2
        for (int k0 = 0; k0 < 128; k0 += 16) {
            uint32_t a[4];
            ldm_x4(a, aBase + k0 * 2);
            #pragma unroll
            for (int j = 0; j < 8; j++) {
                uint32_t b[4];
                ldm_x4(b, bBase + (uint32_t)(j * 16 * STR + k0) * 2);
                mma_bf16(acc[2 * j],     a, b[0], b[1]);
                mma_bf16(acc[2 * j + 1], a, b[2], b[3]);
            }
        }
    }
    __syncthreads();

    {
        float* ep = (float*)(smem + SM_EP);
        const int r0 = wr + (lane >> 2);
        const int cq = 2 * (lane & 3);
        #pragma unroll
        for (int t = 0; t < 16; t++) {
            int col = t * 8 + cq;
            *(float2*)(ep + r0 * EPSTR + col)       = make_float2(acc[t][0], acc[t][1]);
            *(float2*)(ep + (r0 + 8) * EPSTR + col) = make_float2(acc[t][2], acc[t][3]);
        }
    }
    __syncthreads();
    {
        const float*  ep  = (const float*)(smem + SM_EP);
        const float4* g1v = (const float4*)(smem + SM_G1);
        const float4* g2v = (const float4*)(smem + SM_G2);
        const float4* g3v = (const float4*)(smem + SM_G3);
        #pragma unroll 4
        for (int i = tid; i < 64 * 32; i += 128) {
            int r = i >> 5, c4 = i & 31;
            int row = rowBase + r;
            if (row < N) {
                float s1 = __ldg(&c1[row]);
                float s2 = __ldg(&c2[row]);
                float s3 = __ldg(&du[row]);
                float4 v  = *(const float4*)(ep + r * EPSTR + c4 * 4);
                float4 a1 = g1v[c4], a2 = g2v[c4], a3 = g3v[c4];
                v.x += s1 * a1.x + s2 * a2.x + s3 * a3.x;
                v.y += s1 * a1.y + s2 * a2.y + s3 * a3.y;
                v.z += s1 * a1.z + s2 * a2.z + s3 * a3.z;
                v.w += s1 * a1.w + s2 * a2.w + s3 * a3.w;
                *(float4*)(Y + (size_t)row * D + c4 * 4) = v;
            }
        }
    }
}

// ---------------------------------------------------------------------------
// Small fp32 GEMMs for the weight chain.
// ---------------------------------------------------------------------------
__global__ __launch_bounds__(128)
void small_gemm_kernel(const float* __restrict__ A, const float* __restrict__ B,
                       const float* __restrict__ v, float* __restrict__ C,
                       float* __restrict__ vout)
{
    __shared__ float sA[128];
    int r = blockIdx.x;
    int j = threadIdx.x;
    const float* arow = (r < 128) ? (A + (size_t)r * D) : v;
    sA[j] = arow[j];
    __syncthreads();
    float s = 0.f;
    #pragma unroll 8
    for (int k = 0; k < 128; k++) s += sA[k] * B[k * D + j];
    if (r < 128) C[(size_t)r * D + j] = s;
    else vout[j] = s;
}

__global__ __launch_bounds__(128)
void small_gemm_split_kernel(const float* __restrict__ A, const float* __restrict__ B,
                             const float* __restrict__ v,
                             __nv_bfloat16* __restrict__ wthi,
                             __nv_bfloat16* __restrict__ wtlo,
                             float* __restrict__ vout)
{
    __shared__ float sA[128];
    int r = blockIdx.x;
    int j = threadIdx.x;
    const float* arow = (r < 128) ? (A + (size_t)r * D) : v;
    sA[j] = arow[j];
    __syncthreads();
    float s = 0.f;
    #pragma unroll 8
    for (int k = 0; k < 128; k++) s += sA[k] * B[k * D + j];
    if (r < 128) {
        __nv_bfloat16 h, l;
        bf16_split(s, h, l);
        wthi[(size_t)j * D + r] = h;
        wtlo[(size_t)j * D + r] = l;
    } else {
        vout[j] = s;
    }
}

// ---------------------------------------------------------------------------
// CSR build (counting sort by destination).
// ---------------------------------------------------------------------------
__global__ __launch_bounds__(256)
void zero_int_kernel(int* __restrict__ p, int n)
{
    int i = blockIdx.x * blockDim.x + threadIdx.x;
    int stride = gridDim.x * blockDim.x;
    for (; i < n; i += stride) p[i] = 0;
}

__global__ __launch_bounds__(256)
void hist_kernel(const int* __restrict__ dest, int E, int* __restrict__ cnt)
{
    int i = blockIdx.x * blockDim.x + threadIdx.x;
    int stride = gridDim.x * blockDim.x;
    for (; i < E; i += stride) atomicAdd(&cnt[dest[i]], 1);
}

// scanA: shfl-based block scan; emits per-block exclusive rowptr, block sums,
// and float degrees.
__global__ __launch_bounds__(1024)
void scanA_kernel(const int* __restrict__ cnt, int* __restrict__ rowptr,
                  int* __restrict__ bsum, float* __restrict__ deg, int n)
{
    __shared__ int wsum[32];
    int t = threadIdx.x;
    int i = blockIdx.x * 1024 + t;
    int x = (i < n) ? cnt[i] : 0;
    if (i < n) deg[i] = (float)x;

    int v = x;
    #pragma unroll
    for (int o = 1; o < 32; o <<= 1) {
        int y = __shfl_up_sync(0xFFFFFFFFu, v, o);
        if ((t & 31) >= o) v += y;
    }
    if ((t & 31) == 31) wsum[t >> 5] = v;
    __syncthreads();
    if (t < 32) {
        int w = wsum[t];
        #pragma unroll
        for (int o = 1; o < 32; o <<= 1) {
            int y = __shfl_up_sync(0xFFFFFFFFu, w, o);
            if (t >= o) w += y;
        }
        wsum[t] = w;
    }
    __syncthreads();
    int base = (t >= 32) ? wsum[(t >> 5) - 1] : 0;
    int incl = v + base;
    if (i < n) rowptr[i] = incl - x;
    if (t == 1023) bsum[blockIdx.x] = incl;
}

// scanC: integrates the block-sum prefix (reads raw bsum block totals).
__global__ __launch_bounds__(1024)
void scanC_kernel(int* __restrict__ rowptr, int* __restrict__ off,
                  const int* __restrict__ bsum, int n, int E)
{
    __shared__ int blockOff;
    int t = threadIdx.x;
    if (t < 32) {
        int acc = 0;
        for (int j = t; j < blockIdx.x; j += 32) acc += __ldg(&bsum[j]);
        #pragma unroll
        for (int o = 16; o; o >>= 1) acc += __shfl_down_sync(0xFFFFFFFFu, acc, o);
        if (t == 0) blockOff = acc;
    }
    __syncthreads();
    int i = blockIdx.x * 1024 + t;
    if (i < n) {
        int r = rowptr[i] + blockOff;
        rowptr[i] = r;
        off[i] = r;
    }
    if (i == 0) rowptr[n] = E;
}

__global__ __launch_bounds__(256)
void fill_kernel(const int* __restrict__ dest, const int* __restrict__ src,
                 int E, int* __restrict__ off, int* __restrict__ srcs)
{
    int i = blockIdx.x * blockDim.x + threadIdx.x;
    int stride = gridDim.x * blockDim.x;
    for (; i < E; i += stride) {
        int d = dest[i];
        int p = atomicAdd(&off[d], 1);
        srcs[p] = src[i];
    }
}

// ---------------------------------------------------------------------------
// Scalar segment-sums.
// ---------------------------------------------------------------------------
__global__ __launch_bounds__(256)
void scalar_agg_kernel(const float* __restrict__ src, float* __restrict__ dst,
                       const int* __restrict__ rowptr, const int* __restrict__ srcs,
                       int N)
{
    int d = blockIdx.x * 256 + threadIdx.x;
    if (d >= N) return;
    int b = __ldg(&rowptr[d]), e = __ldg(&rowptr[d + 1]);
    float s = 0.f;
    for (int i = b; i < e; i++) s += __ldg(&src[__ldg(&srcs[i])]);
    dst[d] = s;
}

__global__ __launch_bounds__(256)
void c1c2_kernel(const float* __restrict__ ev, const float* __restrict__ dv,
                 float* __restrict__ c1, float* __restrict__ c2,
                 const int* __restrict__ rowptr, const int* __restrict__ srcs,
                 int N)
{
    int d = blockIdx.x * 256 + threadIdx.x;
    if (d >= N) return;
    int b = __ldg(&rowptr[d]), e = __ldg(&rowptr[d + 1]);
    float s1 = 0.f, s2 = 0.f;
    for (int i = b; i < e; i++) {
        int s = __ldg(&srcs[i]);
        s1 += __ldg(&ev[s]);
        s2 += __ldg(&dv[s]);
    }
    c1[d] = s1;
    c2[d] = s2;
}

// ---------------------------------------------------------------------------
// Feature aggregation kernel (fp32 -> fp32).
// ---------------------------------------------------------------------------
__global__ __launch_bounds__(256)
void csr_aggregate_f32_kernel(const float* __restrict__ src,
                              float* __restrict__ dst,
                              const int* __restrict__ rowptr,
                              const int* __restrict__ srcs,
                              int N)
{
    int d = blockIdx.x * 8 + (threadIdx.x >> 5);
    if (d >= N) return;
    int lane = threadIdx.x & 31;
    float4 acc = csr_gather_row(src, srcs, __ldg(&rowptr[d]), __ldg(&rowptr[d + 1]), lane);
    reinterpret_cast<float4*>(dst + (size_t)d * D)[lane] = acc;
}

// ---------------------------------------------------------------------------
extern "C" void kernel_launch(void* const* d_in, const int* in_sizes, int n_in,
                              void* d_out, int out_size)
{
    const float* X_v    = (const float*)d_in[1];
    const int*   edge_u = (const int*)  d_in[2];
    const int*   edge_v = (const int*)  d_in[3];
    const float* W0     = (const float*)d_in[4];
    const float* b0     = (const float*)d_in[5];
    const float* W1     = (const float*)d_in[6];
    const float* b1     = (const float*)d_in[7];
    const float* W2     = (const float*)d_in[8];
    const float* b2     = (const float*)d_in[9];
    float*       out    = (float*)d_out;

    const int N_V = in_sizes[1] / D;
    const int E   = in_sizes[2];
    const int N_U = out_size / D;

    float *bufY, *bufZ, *P, *gg1, *gg2, *du, *dv, *ev, *c1, *c2;
    __nv_bfloat16 *wthi, *wtlo;
    cudaGetSymbolAddress((void**)&bufY, g_bufY);
    cudaGetSymbolAddress((void**)&bufZ, g_bufZ);
    cudaGetSymbolAddress((void**)&P,    g_P);
    cudaGetSymbolAddress((void**)&wthi, g_wthi);
    cudaGetSymbolAddress((void**)&wtlo, g_wtlo);
    cudaGetSymbolAddress((void**)&gg1,  g_g1);
    cudaGetSymbolAddress((void**)&gg2,  g_g2);
    cudaGetSymbolAddress((void**)&du,   g_du);
    cudaGetSymbolAddress((void**)&dv,   g_dv);
    cudaGetSymbolAddress((void**)&ev,   g_ev);
    cudaGetSymbolAddress((void**)&c1,   g_c1);
    cudaGetSymbolAddress((void**)&c2,   g_c2);
    int *rowptr_u, *rowptr_v, *off_u, *off_v, *srcs_u, *srcs_v, *bsum_u, *bsum_v;
    cudaGetSymbolAddress((void**)&rowptr_u, g_rowptr_u);
    cudaGetSymbolAddress((void**)&rowptr_v, g_rowptr_v);
    cudaGetSymbolAddress((void**)&off_u, g_off_u);
    cudaGetSymbolAddress((void**)&off_v, g_off_v);
    cudaGetSymbolAddress((void**)&srcs_u, g_srcs_u);
    cudaGetSymbolAddress((void**)&srcs_v, g_srcs_v);
    cudaGetSymbolAddress((void**)&bsum_u, g_bsum_u);
    cudaGetSymbolAddress((void**)&bsum_v, g_bsum_v);

    cudaFuncSetAttribute(gemm_fused_kernel,
                         cudaFuncAttributeMaxDynamicSharedMemorySize, SM_TOT);

    static cudaStream_t sV = nullptr, sW = nullptr;
    static cudaEvent_t eFork = nullptr, eU = nullptr, eBV = nullptr,
                       eSC = nullptr, eW = nullptr;
    if (sV == nullptr) {
        cudaStreamCreateWithFlags(&sV, cudaStreamNonBlocking);
        cudaStreamCreateWithFlags(&sW, cudaStreamNonBlocking);
        cudaEventCreateWithFlags(&eFork, cudaEventDisableTiming);
        cudaEventCreateWithFlags(&eU,    cudaEventDisableTiming);
        cudaEventCreateWithFlags(&eBV,   cudaEventDisableTiming);
        cudaEventCreateWithFlags(&eSC,   cudaEventDisableTiming);
        cudaEventCreateWithFlags(&eW,    cudaEventDisableTiming);
    }

    const int nb_u = (N_U + 1023) / 1024;
    const int nb_v = (N_V + 1023) / 1024;
    const int aggBlocksU = (N_U + 7) / 8;
    const int aggBlocksV = (N_V + 7) / 8;
    const int gemmBlocksU = (N_U + 63) / 64;

    // ---- fork ----
    cudaEventRecord(eFork, 0);
    cudaStreamWaitEvent(sV, eFork, 0);
    cudaStreamWaitEvent(sW, eFork, 0);

    // ---- main stream: build_u (v2u CSR) ----
    zero_int_kernel<<<(N_U + 255) / 256, 256, 0, 0>>>(off_u, N_U);
    hist_kernel<<<256, 256, 0, 0>>>(edge_u, E, off_u);
    scanA_kernel<<<nb_u, 1024, 0, 0>>>(off_u, rowptr_u, bsum_u, du, N_U);
    scanC_kernel<<<nb_u, 1024, 0, 0>>>(rowptr_u, off_u, bsum_u, N_U, E);
    fill_kernel<<<512, 256, 0, 0>>>(edge_u, edge_v, E, off_u, srcs_u);
    cudaEventRecord(eU, 0);

    // ---- stream V: build_v (u2v CSR) + scalar-degree chain ----
    zero_int_kernel<<<(N_V + 255) / 256, 256, 0, sV>>>(off_v, N_V);
    hist_kernel<<<256, 256, 0, sV>>>(edge_v, E, off_v);
    scanA_kernel<<<nb_v, 1024, 0, sV>>>(off_v, rowptr_v, bsum_v, dv, N_V);
    scanC_kernel<<<nb_v, 1024, 0, sV>>>(rowptr_v, off_v, bsum_v, N_V, E);
    fill_kernel<<<512, 256, 0, sV>>>(edge_v, edge_u, E, off_v, srcs_v);
    cudaEventRecord(eBV, sV);
    cudaStreamWaitEvent(sV, eU, 0);
    scalar_agg_kernel<<<(N_V + 255) / 256, 256, 0, sV>>>(du, ev, rowptr_v, srcs_v, N_V);
    c1c2_kernel<<<(N_U + 255) / 256, 256, 0, sV>>>(ev, dv, c1, c2, rowptr_u, srcs_u, N_U);
    cudaEventRecord(eSC, sV);

    // ---- stream W: weight chain ----
    small_gemm_kernel<<<129, 128, 0, sW>>>(W1, W2, b1, P, gg2);
    small_gemm_split_kernel<<<129, 128, 0, sW>>>(W0, P, b0, wthi, wtlo, gg1);
    cudaEventRecord(eW, sW);

    // ---- main stream: feature aggregation chain ----
    csr_aggregate_f32_kernel<<<aggBlocksU, 256, 0, 0>>>(X_v, bufY, rowptr_u, srcs_u, N_U);
    cudaStreamWaitEvent(0, eBV, 0);
    csr_aggregate_f32_kernel<<<aggBlocksV, 256, 0, 0>>>(bufY, bufZ, rowptr_v, srcs_v, N_V);

    // ---- join + fused gather+GEMM ----
    cudaStreamWaitEvent(0, eSC, 0);
    cudaStreamWaitEvent(0, eW, 0);
    gemm_fused_kernel<<<gemmBlocksU, 128, SM_TOT, 0>>>(bufZ, rowptr_u, srcs_u,
                                                       wthi, wtlo,
                                                       gg1, gg2, b2, c1, c2, du,
                                                       out, N_U);
}

// round 9
// speedup vs baseline: 1.4341x; 1.4341x over previous
#include <cuda_runtime.h>
#include <cuda_bf16.h>
#include <cstdint>

#define D 128
#define MAXN 50176
#define MAXE 640000

typedef unsigned long long u64;

// ---------------------------------------------------------------------------
// Scratch (no cudaMalloc allowed).
// ---------------------------------------------------------------------------
__device__ float         g_bufY[(size_t)MAXN * D];   // S_u = v2u(X_v)
__device__ float         g_bufZ[(size_t)MAXN * D];   // T_v = u2v(S_u)
__device__ __nv_bfloat16 g_hi[(size_t)MAXN * D];     // R split hi
__device__ __nv_bfloat16 g_lo[(size_t)MAXN * D];     // R split lo
__device__ float         g_P[D * D];                 // W1@W2
__device__ __nv_bfloat16 g_wthi[D * D];              // (W0@W1@W2)^T split
__device__ __nv_bfloat16 g_wtlo[D * D];
__device__ float         g_g1[D];                    // b0@W1@W2
__device__ float         g_g2[D];                    // b1@W2
__device__ float         g_du[MAXN];
__device__ float         g_dv[MAXN];
__device__ float         g_ev[MAXN];                 // u2v(d_u)
__device__ float         g_c1[MAXN];                 // v2u(e_v)
__device__ float         g_c2[MAXN];                 // v2u(d_v)

// CSR structures.
__device__ int g_rowptr_u[MAXN + 1];
__device__ int g_rowptr_v[MAXN + 1];
__device__ int g_off_u[MAXN];
__device__ int g_off_v[MAXN];
__device__ int g_srcs_u[MAXE];
__device__ int g_srcs_v[MAXE];
__device__ int g_bsum_u[64];
__device__ int g_bsum_v[64];

// ---------------------------------------------------------------------------
// mma.sync / ldmatrix helpers (baseline PTX, works on compute_103)
// ---------------------------------------------------------------------------
__device__ __forceinline__ uint32_t smem_u32(const void* p) {
    uint32_t a;
    asm("{ .reg .u64 t; cvta.to.shared.u64 t, %1; cvt.u32.u64 %0, t; }" : "=r"(a) : "l"(p));
    return a;
}

__device__ __forceinline__ void ldm_x4(uint32_t (&r)[4], uint32_t addr) {
    asm volatile("ldmatrix.sync.aligned.m8n8.x4.shared.b16 {%0,%1,%2,%3}, [%4];"
                 : "=r"(r[0]), "=r"(r[1]), "=r"(r[2]), "=r"(r[3]) : "r"(addr));
}

__device__ __forceinline__ void mma_bf16(float (&c)[4], const uint32_t (&a)[4],
                                         uint32_t b0, uint32_t b1) {
    asm volatile(
        "mma.sync.aligned.m16n8k16.row.col.f32.bf16.bf16.f32 "
        "{%0,%1,%2,%3}, {%4,%5,%6,%7}, {%8,%9}, {%0,%1,%2,%3};"
        : "+f"(c[0]), "+f"(c[1]), "+f"(c[2]), "+f"(c[3])
        : "r"(a[0]), "r"(a[1]), "r"(a[2]), "r"(a[3]), "r"(b0), "r"(b1));
}

__device__ __forceinline__ void bf16_split(float f, __nv_bfloat16& h, __nv_bfloat16& l) {
    h = __float2bfloat16(f);
    l = __float2bfloat16(f - __bfloat162float(h));
}

// ---------------------------------------------------------------------------
// Final tensor GEMM: out[64-row tile] = R @ W012 + c1*g1 + c2*g2 + du*g3
// ---------------------------------------------------------------------------
#define STR 136
#define SM_G1   0
#define SM_G2   512
#define SM_G3   1024
#define SM_AHI  1536
#define SM_ALO  (SM_AHI + 64 * 272)
#define SM_BHI  (SM_ALO + 64 * 272)
#define SM_BLO  (SM_BHI + 128 * 272)
#define SM_TOT  (SM_BLO + 128 * 272)     // 105984
#define SM_EP   1536
#define EPSTR   132

__global__ __launch_bounds__(128, 2)
void gemm_final_kernel(const __nv_bfloat16* __restrict__ Ahi,
                       const __nv_bfloat16* __restrict__ Alo,
                       const __nv_bfloat16* __restrict__ Bhi,
                       const __nv_bfloat16* __restrict__ Blo,
                       const float* __restrict__ g1,
                       const float* __restrict__ g2,
                       const float* __restrict__ g3,
                       const float* __restrict__ c1,
                       const float* __restrict__ c2,
                       const float* __restrict__ du,
                       float* __restrict__ Y,
                       int N)
{
    extern __shared__ char smem[];
    const uint32_t sb = smem_u32(smem);
    const int tid  = threadIdx.x;
    const int lane = tid & 31;
    const int warp = tid >> 5;
    const int rowBase = blockIdx.x * 64;

    ((float*)(smem + SM_G1))[tid] = g1[tid];
    ((float*)(smem + SM_G2))[tid] = g2[tid];
    ((float*)(smem + SM_G3))[tid] = g3[tid];

    #pragma unroll 4
    for (int i = tid; i < 128 * 16; i += 128) {
        int n = i >> 4, c = i & 15;
        uint32_t so = (uint32_t)(n * 272 + c * 16);
        *(uint4*)(smem + SM_BHI + so) = *(const uint4*)(Bhi + (size_t)n * D + c * 8);
        *(uint4*)(smem + SM_BLO + so) = *(const uint4*)(Blo + (size_t)n * D + c * 8);
    }
    #pragma unroll 4
    for (int i = tid; i < 64 * 16; i += 128) {
        int r = i >> 4, c = i & 15;
        int row = rowBase + r;
        uint4 vh = make_uint4(0, 0, 0, 0), vl = vh;
        if (row < N) {
            vh = *(const uint4*)(Ahi + (size_t)row * D + c * 8);
            vl = *(const uint4*)(Alo + (size_t)row * D + c * 8);
        }
        uint32_t so = (uint32_t)(r * 272 + c * 16);
        *(uint4*)(smem + SM_AHI + so) = vh;
        *(uint4*)(smem + SM_ALO + so) = vl;
    }
    __syncthreads();

    float acc[16][4];
    #pragma unroll
    for (int t = 0; t < 16; t++) {
        acc[t][0] = 0.f; acc[t][1] = 0.f; acc[t][2] = 0.f; acc[t][3] = 0.f;
    }

    const int wr = warp * 16;
    const uint32_t aRowOff = (uint32_t)((wr + (lane & 15)) * STR + ((lane >> 4) << 3)) * 2;
    const int nOff  = (lane & 7) + ((lane >> 4) & 1) * 8;
    const int kHalf = ((lane >> 3) & 1) * 8;
    const uint32_t bRowOff = (uint32_t)(nOff * STR + kHalf) * 2;

    #pragma unroll 1
    for (int pass = 0; pass < 3; pass++) {
        uint32_t aBase = sb + ((pass == 2) ? SM_ALO : SM_AHI) + aRowOff;
        uint32_t bBase = sb + ((pass == 1) ? SM_BLO : SM_BHI) + bRowOff;
        #pragma unroll 2
        for (int k0 = 0; k0 < 128; k0 += 16) {
            uint32_t a[4];
            ldm_x4(a, aBase + k0 * 2);
            #pragma unroll
            for (int j = 0; j < 8; j++) {
                uint32_t b[4];
                ldm_x4(b, bBase + (uint32_t)(j * 16 * STR + k0) * 2);
                mma_bf16(acc[2 * j],     a, b[0], b[1]);
                mma_bf16(acc[2 * j + 1], a, b[2], b[3]);
            }
        }
    }
    __syncthreads();

    {
        float* ep = (float*)(smem + SM_EP);
        const int r0 = wr + (lane >> 2);
        const int cq = 2 * (lane & 3);
        #pragma unroll
        for (int t = 0; t < 16; t++) {
            int col = t * 8 + cq;
            *(float2*)(ep + r0 * EPSTR + col)       = make_float2(acc[t][0], acc[t][1]);
            *(float2*)(ep + (r0 + 8) * EPSTR + col) = make_float2(acc[t][2], acc[t][3]);
        }
    }
    __syncthreads();
    {
        const float*  ep  = (const float*)(smem + SM_EP);
        const float4* g1v = (const float4*)(smem + SM_G1);
        const float4* g2v = (const float4*)(smem + SM_G2);
        const float4* g3v = (const float4*)(smem + SM_G3);
        #pragma unroll 4
        for (int i = tid; i < 64 * 32; i += 128) {
            int r = i >> 5, c4 = i & 31;
            int row = rowBase + r;
            if (row < N) {
                float s1 = __ldg(&c1[row]);
                float s2 = __ldg(&c2[row]);
                float s3 = __ldg(&du[row]);
                float4 v  = *(const float4*)(ep + r * EPSTR + c4 * 4);
                float4 a1 = g1v[c4], a2 = g2v[c4], a3 = g3v[c4];
                v.x += s1 * a1.x + s2 * a2.x + s3 * a3.x;
                v.y += s1 * a1.y + s2 * a2.y + s3 * a3.y;
                v.z += s1 * a1.z + s2 * a2.z + s3 * a3.z;
                v.w += s1 * a1.w + s2 * a2.w + s3 * a3.w;
                *(float4*)(Y + (size_t)row * D + c4 * 4) = v;
            }
        }
    }
}

// ---------------------------------------------------------------------------
// Small fp32 GEMMs for the weight chain.
// ---------------------------------------------------------------------------
__global__ __launch_bounds__(128)
void small_gemm_kernel(const float* __restrict__ A, const float* __restrict__ B,
                       const float* __restrict__ v, float* __restrict__ C,
                       float* __restrict__ vout)
{
    __shared__ float sA[128];
    int r = blockIdx.x;
    int j = threadIdx.x;
    const float* arow = (r < 128) ? (A + (size_t)r * D) : v;
    sA[j] = arow[j];
    __syncthreads();
    float s = 0.f;
    #pragma unroll 8
    for (int k = 0; k < 128; k++) s += sA[k] * B[k * D + j];
    if (r < 128) C[(size_t)r * D + j] = s;
    else vout[j] = s;
}

__global__ __launch_bounds__(128)
void small_gemm_split_kernel(const float* __restrict__ A, const float* __restrict__ B,
                             const float* __restrict__ v,
                             __nv_bfloat16* __restrict__ wthi,
                             __nv_bfloat16* __restrict__ wtlo,
                             float* __restrict__ vout)
{
    __shared__ float sA[128];
    int r = blockIdx.x;
    int j = threadIdx.x;
    const float* arow = (r < 128) ? (A + (size_t)r * D) : v;
    sA[j] = arow[j];
    __syncthreads();
    float s = 0.f;
    #pragma unroll 8
    for (int k = 0; k < 128; k++) s += sA[k] * B[k * D + j];
    if (r < 128) {
        __nv_bfloat16 h, l;
        bf16_split(s, h, l);
        wthi[(size_t)j * D + r] = h;
        wtlo[(size_t)j * D + r] = l;
    } else {
        vout[j] = s;
    }
}

// ---------------------------------------------------------------------------
// CSR build (counting sort by destination).
// ---------------------------------------------------------------------------
__global__ __launch_bounds__(256)
void zero_int_kernel(int* __restrict__ p, int n)
{
    int i = blockIdx.x * blockDim.x + threadIdx.x;
    int stride = gridDim.x * blockDim.x;
    for (; i < n; i += stride) p[i] = 0;
}

__global__ __launch_bounds__(256)
void hist_kernel(const int* __restrict__ dest, int E, int* __restrict__ cnt)
{
    int i = blockIdx.x * blockDim.x + threadIdx.x;
    int stride = gridDim.x * blockDim.x;
    for (; i < E; i += stride) atomicAdd(&cnt[dest[i]], 1);
}

// scanA: shfl-based block scan; emits per-block exclusive rowptr, block sums,
// and float degrees.
__global__ __launch_bounds__(1024)
void scanA_kernel(const int* __restrict__ cnt, int* __restrict__ rowptr,
                  int* __restrict__ bsum, float* __restrict__ deg, int n)
{
    __shared__ int wsum[32];
    int t = threadIdx.x;
    int i = blockIdx.x * 1024 + t;
    int x = (i < n) ? cnt[i] : 0;
    if (i < n) deg[i] = (float)x;

    int v = x;
    #pragma unroll
    for (int o = 1; o < 32; o <<= 1) {
        int y = __shfl_up_sync(0xFFFFFFFFu, v, o);
        if ((t & 31) >= o) v += y;
    }
    if ((t & 31) == 31) wsum[t >> 5] = v;
    __syncthreads();
    if (t < 32) {
        int w = wsum[t];
        #pragma unroll
        for (int o = 1; o < 32; o <<= 1) {
            int y = __shfl_up_sync(0xFFFFFFFFu, w, o);
            if (t >= o) w += y;
        }
        wsum[t] = w;
    }
    __syncthreads();
    int base = (t >= 32) ? wsum[(t >> 5) - 1] : 0;
    int incl = v + base;
    if (i < n) rowptr[i] = incl - x;
    if (t == 1023) bsum[blockIdx.x] = incl;
}

// scanC: integrates the block-sum prefix in-kernel (no separate scanB launch).
__global__ __launch_bounds__(1024)
void scanC_kernel(int* __restrict__ rowptr, int* __restrict__ off,
                  const int* __restrict__ bsum, int n, int E)
{
    __shared__ int blockOff;
    int t = threadIdx.x;
    if (t < 32) {
        int acc = 0;
        for (int j = t; j < blockIdx.x; j += 32) acc += __ldg(&bsum[j]);
        #pragma unroll
        for (int o = 16; o; o >>= 1) acc += __shfl_down_sync(0xFFFFFFFFu, acc, o);
        if (t == 0) blockOff = acc;
    }
    __syncthreads();
    int i = blockIdx.x * 1024 + t;
    if (i < n) {
        int r = rowptr[i] + blockOff;
        rowptr[i] = r;
        off[i] = r;
    }
    if (i == 0) rowptr[n] = E;
}

__global__ __launch_bounds__(256)
void fill_kernel(const int* __restrict__ dest, const int* __restrict__ src,
                 int E, int* __restrict__ off, int* __restrict__ srcs)
{
    int i = blockIdx.x * blockDim.x + threadIdx.x;
    int stride = gridDim.x * blockDim.x;
    for (; i < E; i += stride) {
        int d = dest[i];
        int p = atomicAdd(&off[d], 1);
        srcs[p] = src[i];
    }
}

// ---------------------------------------------------------------------------
// Scalar segment-sums.
// ---------------------------------------------------------------------------
__global__ __launch_bounds__(256)
void scalar_agg_kernel(const float* __restrict__ src, float* __restrict__ dst,
                       const int* __restrict__ rowptr, const int* __restrict__ srcs,
                       int N)
{
    int d = blockIdx.x * 256 + threadIdx.x;
    if (d >= N) return;
    int b = __ldg(&rowptr[d]), e = __ldg(&rowptr[d + 1]);
    float s = 0.f;
    for (int i = b; i < e; i++) s += __ldg(&src[__ldg(&srcs[i])]);
    dst[d] = s;
}

__global__ __launch_bounds__(256)
void c1c2_kernel(const float* __restrict__ ev, const float* __restrict__ dv,
                 float* __restrict__ c1, float* __restrict__ c2,
                 const int* __restrict__ rowptr, const int* __restrict__ srcs,
                 int N)
{
    int d = blockIdx.x * 256 + threadIdx.x;
    if (d >= N) return;
    int b = __ldg(&rowptr[d]), e = __ldg(&rowptr[d + 1]);
    float s1 = 0.f, s2 = 0.f;
    for (int i = b; i < e; i++) {
        int s = __ldg(&srcs[i]);
        s1 += __ldg(&ev[s]);
        s2 += __ldg(&dv[s]);
    }
    c1[d] = s1;
    c2[d] = s2;
}

// ---------------------------------------------------------------------------
// CSR feature aggregation. One warp per dest row; fp32 accumulation.
// ---------------------------------------------------------------------------
__device__ __forceinline__ float4 csr_gather_row(const float* __restrict__ src,
                                                 const int* __restrict__ srcs,
                                                 int beg, int end, int lane)
{
    float4 acc = make_float4(0.f, 0.f, 0.f, 0.f);
    int i = beg;
    for (; i + 4 <= end; i += 4) {
        int s0 = __ldg(&srcs[i + 0]);
        int s1 = __ldg(&srcs[i + 1]);
        int s2 = __ldg(&srcs[i + 2]);
        int s3 = __ldg(&srcs[i + 3]);
        float4 a = __ldg(reinterpret_cast<const float4*>(src + (size_t)s0 * D) + lane);
        float4 b = __ldg(reinterpret_cast<const float4*>(src + (size_t)s1 * D) + lane);
        float4 c = __ldg(reinterpret_cast<const float4*>(src + (size_t)s2 * D) + lane);
        float4 e = __ldg(reinterpret_cast<const float4*>(src + (size_t)s3 * D) + lane);
        acc.x += (a.x + b.x) + (c.x + e.x);
        acc.y += (a.y + b.y) + (c.y + e.y);
        acc.z += (a.z + b.z) + (c.z + e.z);
        acc.w += (a.w + b.w) + (c.w + e.w);
    }
    for (; i < end; i++) {
        int s0 = __ldg(&srcs[i]);
        float4 a = __ldg(reinterpret_cast<const float4*>(src + (size_t)s0 * D) + lane);
        acc.x += a.x; acc.y += a.y; acc.z += a.z; acc.w += a.w;
    }
    return acc;
}

__global__ __launch_bounds__(256)
void csr_aggregate_f32_kernel(const float* __restrict__ src,
                              float* __restrict__ dst,
                              const int* __restrict__ rowptr,
                              const int* __restrict__ srcs,
                              int N)
{
    int d = blockIdx.x * 8 + (threadIdx.x >> 5);
    if (d >= N) return;
    int lane = threadIdx.x & 31;
    float4 acc = csr_gather_row(src, srcs, __ldg(&rowptr[d]), __ldg(&rowptr[d + 1]), lane);
    reinterpret_cast<float4*>(dst + (size_t)d * D)[lane] = acc;
}

__global__ __launch_bounds__(256)
void csr_aggregate_split_kernel(const float* __restrict__ src,
                                __nv_bfloat16* __restrict__ dhi,
                                __nv_bfloat16* __restrict__ dlo,
                                const int* __restrict__ rowptr,
                                const int* __restrict__ srcs,
                                int N)
{
    int d = blockIdx.x * 8 + (threadIdx.x >> 5);
    if (d >= N) return;
    int lane = threadIdx.x & 31;
    float4 acc = csr_gather_row(src, srcs, __ldg(&rowptr[d]), __ldg(&rowptr[d + 1]), lane);

    __nv_bfloat16 h0, l0, h1, l1, h2, l2, h3, l3;
    bf16_split(acc.x, h0, l0); bf16_split(acc.y, h1, l1);
    bf16_split(acc.z, h2, l2); bf16_split(acc.w, h3, l3);
    __nv_bfloat162 hi01 = __nv_bfloat162(h0, h1), hi23 = __nv_bfloat162(h2, h3);
    __nv_bfloat162 lo01 = __nv_bfloat162(l0, l1), lo23 = __nv_bfloat162(l2, l3);
    uint2 hv, lv;
    hv.x = *(uint32_t*)&hi01; hv.y = *(uint32_t*)&hi23;
    lv.x = *(uint32_t*)&lo01; lv.y = *(uint32_t*)&lo23;
    *(uint2*)(dhi + (size_t)d * D + lane * 4) = hv;
    *(uint2*)(dlo + (size_t)d * D + lane * 4) = lv;
}

// ---------------------------------------------------------------------------
extern "C" void kernel_launch(void* const* d_in, const int* in_sizes, int n_in,
                              void* d_out, int out_size)
{
    const float* X_v    = (const float*)d_in[1];
    const int*   edge_u = (const int*)  d_in[2];
    const int*   edge_v = (const int*)  d_in[3];
    const float* W0     = (const float*)d_in[4];
    const float* b0     = (const float*)d_in[5];
    const float* W1     = (const float*)d_in[6];
    const float* b1     = (const float*)d_in[7];
    const float* W2     = (const float*)d_in[8];
    const float* b2     = (const float*)d_in[9];
    float*       out    = (float*)d_out;

    const int N_V = in_sizes[1] / D;
    const int E   = in_sizes[2];
    const int N_U = out_size / D;

    float *bufY, *bufZ, *P, *gg1, *gg2, *du, *dv, *ev, *c1, *c2;
    __nv_bfloat16 *hi, *lo, *wthi, *wtlo;
    cudaGetSymbolAddress((void**)&bufY, g_bufY);
    cudaGetSymbolAddress((void**)&bufZ, g_bufZ);
    cudaGetSymbolAddress((void**)&hi,   g_hi);
    cudaGetSymbolAddress((void**)&lo,   g_lo);
    cudaGetSymbolAddress((void**)&P,    g_P);
    cudaGetSymbolAddress((void**)&wthi, g_wthi);
    cudaGetSymbolAddress((void**)&wtlo, g_wtlo);
    cudaGetSymbolAddress((void**)&gg1,  g_g1);
    cudaGetSymbolAddress((void**)&gg2,  g_g2);
    cudaGetSymbolAddress((void**)&du,   g_du);
    cudaGetSymbolAddress((void**)&dv,   g_dv);
    cudaGetSymbolAddress((void**)&ev,   g_ev);
    cudaGetSymbolAddress((void**)&c1,   g_c1);
    cudaGetSymbolAddress((void**)&c2,   g_c2);
    int *rowptr_u, *rowptr_v, *off_u, *off_v, *srcs_u, *srcs_v, *bsum_u, *bsum_v;
    cudaGetSymbolAddress((void**)&rowptr_u, g_rowptr_u);
    cudaGetSymbolAddress((void**)&rowptr_v, g_rowptr_v);
    cudaGetSymbolAddress((void**)&off_u, g_off_u);
    cudaGetSymbolAddress((void**)&off_v, g_off_v);
    cudaGetSymbolAddress((void**)&srcs_u, g_srcs_u);
    cudaGetSymbolAddress((void**)&srcs_v, g_srcs_v);
    cudaGetSymbolAddress((void**)&bsum_u, g_bsum_u);
    cudaGetSymbolAddress((void**)&bsum_v, g_bsum_v);

    cudaFuncSetAttribute(gemm_final_kernel,
                         cudaFuncAttributeMaxDynamicSharedMemorySize, SM_TOT);

    static cudaStream_t sV = nullptr, sW = nullptr;
    static cudaEvent_t eFork = nullptr, eU = nullptr, eBV = nullptr,
                       eSC = nullptr, eW = nullptr;
    if (sV == nullptr) {
        cudaStreamCreateWithFlags(&sV, cudaStreamNonBlocking);
        cudaStreamCreateWithFlags(&sW, cudaStreamNonBlocking);
        cudaEventCreateWithFlags(&eFork, cudaEventDisableTiming);
        cudaEventCreateWithFlags(&eU,    cudaEventDisableTiming);
        cudaEventCreateWithFlags(&eBV,   cudaEventDisableTiming);
        cudaEventCreateWithFlags(&eSC,   cudaEventDisableTiming);
        cudaEventCreateWithFlags(&eW,    cudaEventDisableTiming);
    }

    const int nb_u = (N_U + 1023) / 1024;
    const int nb_v = (N_V + 1023) / 1024;
    const int aggBlocksU = (N_U + 7) / 8;
    const int aggBlocksV = (N_V + 7) / 8;
    const int gemmBlocksU = (N_U + 63) / 64;

    // ---- fork ----
    cudaEventRecord(eFork, 0);
    cudaStreamWaitEvent(sV, eFork, 0);
    cudaStreamWaitEvent(sW, eFork, 0);

    // ---- main stream: build_u (v2u CSR) ----
    zero_int_kernel<<<(N_U + 255) / 256, 256, 0, 0>>>(off_u, N_U);
    hist_kernel<<<256, 256, 0, 0>>>(edge_u, E, off_u);
    scanA_kernel<<<nb_u, 1024, 0, 0>>>(off_u, rowptr_u, bsum_u, du, N_U);
    scanC_kernel<<<nb_u, 1024, 0, 0>>>(rowptr_u, off_u, bsum_u, N_U, E);
    fill_kernel<<<512, 256, 0, 0>>>(edge_u, edge_v, E, off_u, srcs_u);
    cudaEventRecord(eU, 0);

    // ---- stream V: build_v (u2v CSR) + scalar-degree chain ----
    zero_int_kernel<<<(N_V + 255) / 256, 256, 0, sV>>>(off_v, N_V);
    hist_kernel<<<256, 256, 0, sV>>>(edge_v, E, off_v);
    scanA_kernel<<<nb_v, 1024, 0, sV>>>(off_v, rowptr_v, bsum_v, dv, N_V);
    scanC_kernel<<<nb_v, 1024, 0, sV>>>(rowptr_v, off_v, bsum_v, N_V, E);
    fill_kernel<<<512, 256, 0, sV>>>(edge_v, edge_u, E, off_v, srcs_v);
    cudaEventRecord(eBV, sV);
    cudaStreamWaitEvent(sV, eU, 0);
    scalar_agg_kernel<<<(N_V + 255) / 256, 256, 0, sV>>>(du, ev, rowptr_v, srcs_v, N_V);
    c1c2_kernel<<<(N_U + 255) / 256, 256, 0, sV>>>(ev, dv, c1, c2, rowptr_u, srcs_u, N_U);
    cudaEventRecord(eSC, sV);

    // ---- stream W: weight chain ----
    small_gemm_kernel<<<129, 128, 0, sW>>>(W1, W2, b1, P, gg2);
    small_gemm_split_kernel<<<129, 128, 0, sW>>>(W0, P, b0, wthi, wtlo, gg1);
    cudaEventRecord(eW, sW);

    // ---- main stream: feature aggregation chain ----
    csr_aggregate_f32_kernel<<<aggBlocksU, 256, 0, 0>>>(X_v, bufY, rowptr_u, srcs_u, N_U);
    cudaStreamWaitEvent(0, eBV, 0);
    csr_aggregate_f32_kernel<<<aggBlocksV, 256, 0, 0>>>(bufY, bufZ, rowptr_v, srcs_v, N_V);
    csr_aggregate_split_kernel<<<aggBlocksU, 256, 0, 0>>>(bufZ, hi, lo, rowptr_u, srcs_u, N_U);

    // ---- join + final GEMM ----
    cudaStreamWaitEvent(0, eSC, 0);
    cudaStreamWaitEvent(0, eW, 0);
    gemm_final_kernel<<<gemmBlocksU, 128, SM_TOT, 0>>>(hi, lo, wthi, wtlo,
                                                       gg1, gg2, b2, c1, c2, du,
                                                       out, N_U);
}

// round 10
// speedup vs baseline: 1.5442x; 1.0768x over previous
#include <cuda_runtime.h>
#include <cuda_bf16.h>
#include <cuda_fp16.h>
#include <cstdint>

#define D 128
#define MAXN 50176
#define MAXE 640000

typedef unsigned long long u64;

// ---------------------------------------------------------------------------
// Scratch (no cudaMalloc allowed).
// ---------------------------------------------------------------------------
__device__ __half        g_bufY[(size_t)MAXN * D];   // S_u = v2u(X_v), fp16
__device__ __half        g_bufZ[(size_t)MAXN * D];   // T_v = u2v(S_u), fp16
__device__ __nv_bfloat16 g_hi[(size_t)MAXN * D];     // R split hi
__device__ __nv_bfloat16 g_lo[(size_t)MAXN * D];     // R split lo
__device__ float         g_P[D * D];                 // W1@W2
__device__ __nv_bfloat16 g_wthi[D * D];              // (W0@W1@W2)^T split
__device__ __nv_bfloat16 g_wtlo[D * D];
__device__ float         g_g1[D];                    // b0@W1@W2
__device__ float         g_g2[D];                    // b1@W2
__device__ float         g_du[MAXN];
__device__ float         g_dv[MAXN];
__device__ float         g_ev[MAXN];                 // u2v(d_u)
__device__ float         g_c1[MAXN];                 // v2u(e_v)
__device__ float         g_c2[MAXN];                 // v2u(d_v)

// CSR structures.
__device__ int g_rowptr_u[MAXN + 1];
__device__ int g_rowptr_v[MAXN + 1];
__device__ int g_off_u[MAXN];
__device__ int g_off_v[MAXN];
__device__ int g_srcs_u[MAXE];
__device__ int g_srcs_v[MAXE];
__device__ int g_bsum_u[64];
__device__ int g_bsum_v[64];

// ---------------------------------------------------------------------------
// mma.sync / ldmatrix helpers (baseline PTX, works on compute_103)
// ---------------------------------------------------------------------------
__device__ __forceinline__ uint32_t smem_u32(const void* p) {
    uint32_t a;
    asm("{ .reg .u64 t; cvta.to.shared.u64 t, %1; cvt.u32.u64 %0, t; }" : "=r"(a) : "l"(p));
    return a;
}

__device__ __forceinline__ void ldm_x4(uint32_t (&r)[4], uint32_t addr) {
    asm volatile("ldmatrix.sync.aligned.m8n8.x4.shared.b16 {%0,%1,%2,%3}, [%4];"
                 : "=r"(r[0]), "=r"(r[1]), "=r"(r[2]), "=r"(r[3]) : "r"(addr));
}

__device__ __forceinline__ void mma_bf16(float (&c)[4], const uint32_t (&a)[4],
                                         uint32_t b0, uint32_t b1) {
    asm volatile(
        "mma.sync.aligned.m16n8k16.row.col.f32.bf16.bf16.f32 "
        "{%0,%1,%2,%3}, {%4,%5,%6,%7}, {%8,%9}, {%0,%1,%2,%3};"
        : "+f"(c[0]), "+f"(c[1]), "+f"(c[2]), "+f"(c[3])
        : "r"(a[0]), "r"(a[1]), "r"(a[2]), "r"(a[3]), "r"(b0), "r"(b1));
}

__device__ __forceinline__ void bf16_split(float f, __nv_bfloat16& h, __nv_bfloat16& l) {
    h = __float2bfloat16(f);
    l = __float2bfloat16(f - __bfloat162float(h));
}

// ---------------------------------------------------------------------------
// Final tensor GEMM: out[64-row tile] = R @ W012 + c1*g1 + c2*g2 + du*g3
// ---------------------------------------------------------------------------
#define STR 136
#define SM_G1   0
#define SM_G2   512
#define SM_G3   1024
#define SM_AHI  1536
#define SM_ALO  (SM_AHI + 64 * 272)
#define SM_BHI  (SM_ALO + 64 * 272)
#define SM_BLO  (SM_BHI + 128 * 272)
#define SM_TOT  (SM_BLO + 128 * 272)     // 105984
#define SM_EP   1536
#define EPSTR   132

__global__ __launch_bounds__(128, 2)
void gemm_final_kernel(const __nv_bfloat16* __restrict__ Ahi,
                       const __nv_bfloat16* __restrict__ Alo,
                       const __nv_bfloat16* __restrict__ Bhi,
                       const __nv_bfloat16* __restrict__ Blo,
                       const float* __restrict__ g1,
                       const float* __restrict__ g2,
                       const float* __restrict__ g3,
                       const float* __restrict__ c1,
                       const float* __restrict__ c2,
                       const float* __restrict__ du,
                       float* __restrict__ Y,
                       int N)
{
    extern __shared__ char smem[];
    const uint32_t sb = smem_u32(smem);
    const int tid  = threadIdx.x;
    const int lane = tid & 31;
    const int warp = tid >> 5;
    const int rowBase = blockIdx.x * 64;

    ((float*)(smem + SM_G1))[tid] = g1[tid];
    ((float*)(smem + SM_G2))[tid] = g2[tid];
    ((float*)(smem + SM_G3))[tid] = g3[tid];

    #pragma unroll 4
    for (int i = tid; i < 128 * 16; i += 128) {
        int n = i >> 4, c = i & 15;
        uint32_t so = (uint32_t)(n * 272 + c * 16);
        *(uint4*)(smem + SM_BHI + so) = *(const uint4*)(Bhi + (size_t)n * D + c * 8);
        *(uint4*)(smem + SM_BLO + so) = *(const uint4*)(Blo + (size_t)n * D + c * 8);
    }
    #pragma unroll 4
    for (int i = tid; i < 64 * 16; i += 128) {
        int r = i >> 4, c = i & 15;
        int row = rowBase + r;
        uint4 vh = make_uint4(0, 0, 0, 0), vl = vh;
        if (row < N) {
            vh = *(const uint4*)(Ahi + (size_t)row * D + c * 8);
            vl = *(const uint4*)(Alo + (size_t)row * D + c * 8);
        }
        uint32_t so = (uint32_t)(r * 272 + c * 16);
        *(uint4*)(smem + SM_AHI + so) = vh;
        *(uint4*)(smem + SM_ALO + so) = vl;
    }
    __syncthreads();

    float acc[16][4];
    #pragma unroll
    for (int t = 0; t < 16; t++) {
        acc[t][0] = 0.f; acc[t][1] = 0.f; acc[t][2] = 0.f; acc[t][3] = 0.f;
    }

    const int wr = warp * 16;
    const uint32_t aRowOff = (uint32_t)((wr + (lane & 15)) * STR + ((lane >> 4) << 3)) * 2;
    const int nOff  = (lane & 7) + ((lane >> 4) & 1) * 8;
    const int kHalf = ((lane >> 3) & 1) * 8;
    const uint32_t bRowOff = (uint32_t)(nOff * STR + kHalf) * 2;

    #pragma unroll 1
    for (int pass = 0; pass < 3; pass++) {
        uint32_t aBase = sb + ((pass == 2) ? SM_ALO : SM_AHI) + aRowOff;
        uint32_t bBase = sb + ((pass == 1) ? SM_BLO : SM_BHI) + bRowOff;
        #pragma unroll 2
        for (int k0 = 0; k0 < 128; k0 += 16) {
            uint32_t a[4];
            ldm_x4(a, aBase + k0 * 2);
            #pragma unroll
            for (int j = 0; j < 8; j++) {
                uint32_t b[4];
                ldm_x4(b, bBase + (uint32_t)(j * 16 * STR + k0) * 2);
                mma_bf16(acc[2 * j],     a, b[0], b[1]);
                mma_bf16(acc[2 * j + 1], a, b[2], b[3]);
            }
        }
    }
    __syncthreads();

    {
        float* ep = (float*)(smem + SM_EP);
        const int r0 = wr + (lane >> 2);
        const int cq = 2 * (lane & 3);
        #pragma unroll
        for (int t = 0; t < 16; t++) {
            int col = t * 8 + cq;
            *(float2*)(ep + r0 * EPSTR + col)       = make_float2(acc[t][0], acc[t][1]);
            *(float2*)(ep + (r0 + 8) * EPSTR + col) = make_float2(acc[t][2], acc[t][3]);
        }
    }
    __syncthreads();
    {
        const float*  ep  = (const float*)(smem + SM_EP);
        const float4* g1v = (const float4*)(smem + SM_G1);
        const float4* g2v = (const float4*)(smem + SM_G2);
        const float4* g3v = (const float4*)(smem + SM_G3);
        #pragma unroll 4
        for (int i = tid; i < 64 * 32; i += 128) {
            int r = i >> 5, c4 = i & 31;
            int row = rowBase + r;
            if (row < N) {
                float s1 = __ldg(&c1[row]);
                float s2 = __ldg(&c2[row]);
                float s3 = __ldg(&du[row]);
                float4 v  = *(const float4*)(ep + r * EPSTR + c4 * 4);
                float4 a1 = g1v[c4], a2 = g2v[c4], a3 = g3v[c4];
                v.x += s1 * a1.x + s2 * a2.x + s3 * a3.x;
                v.y += s1 * a1.y + s2 * a2.y + s3 * a3.y;
                v.z += s1 * a1.z + s2 * a2.z + s3 * a3.z;
                v.w += s1 * a1.w + s2 * a2.w + s3 * a3.w;
                *(float4*)(Y + (size_t)row * D + c4 * 4) = v;
            }
        }
    }
}

// ---------------------------------------------------------------------------
// Small fp32 GEMMs for the weight chain.
// ---------------------------------------------------------------------------
__global__ __launch_bounds__(128)
void small_gemm_kernel(const float* __restrict__ A, const float* __restrict__ B,
                       const float* __restrict__ v, float* __restrict__ C,
                       float* __restrict__ vout)
{
    __shared__ float sA[128];
    int r = blockIdx.x;
    int j = threadIdx.x;
    const float* arow = (r < 128) ? (A + (size_t)r * D) : v;
    sA[j] = arow[j];
    __syncthreads();
    float s = 0.f;
    #pragma unroll 8
    for (int k = 0; k < 128; k++) s += sA[k] * B[k * D + j];
    if (r < 128) C[(size_t)r * D + j] = s;
    else vout[j] = s;
}

__global__ __launch_bounds__(128)
void small_gemm_split_kernel(const float* __restrict__ A, const float* __restrict__ B,
                             const float* __restrict__ v,
                             __nv_bfloat16* __restrict__ wthi,
                             __nv_bfloat16* __restrict__ wtlo,
                             float* __restrict__ vout)
{
    __shared__ float sA[128];
    int r = blockIdx.x;
    int j = threadIdx.x;
    const float* arow = (r < 128) ? (A + (size_t)r * D) : v;
    sA[j] = arow[j];
    __syncthreads();
    float s = 0.f;
    #pragma unroll 8
    for (int k = 0; k < 128; k++) s += sA[k] * B[k * D + j];
    if (r < 128) {
        __nv_bfloat16 h, l;
        bf16_split(s, h, l);
        wthi[(size_t)j * D + r] = h;
        wtlo[(size_t)j * D + r] = l;
    } else {
        vout[j] = s;
    }
}

// ---------------------------------------------------------------------------
// CSR build (counting sort by destination).
// ---------------------------------------------------------------------------
__global__ __launch_bounds__(256)
void zero_int_kernel(int* __restrict__ p, int n)
{
    int i = blockIdx.x * blockDim.x + threadIdx.x;
    int stride = gridDim.x * blockDim.x;
    for (; i < n; i += stride) p[i] = 0;
}

__global__ __launch_bounds__(256)
void hist_kernel(const int* __restrict__ dest, int E, int* __restrict__ cnt)
{
    int i = blockIdx.x * blockDim.x + threadIdx.x;
    int stride = gridDim.x * blockDim.x;
    for (; i < E; i += stride) atomicAdd(&cnt[dest[i]], 1);
}

// scanA: shfl-based block scan; emits per-block exclusive rowptr, block sums,
// and float degrees.
__global__ __launch_bounds__(1024)
void scanA_kernel(const int* __restrict__ cnt, int* __restrict__ rowptr,
                  int* __restrict__ bsum, float* __restrict__ deg, int n)
{
    __shared__ int wsum[32];
    int t = threadIdx.x;
    int i = blockIdx.x * 1024 + t;
    int x = (i < n) ? cnt[i] : 0;
    if (i < n) deg[i] = (float)x;

    int v = x;
    #pragma unroll
    for (int o = 1; o < 32; o <<= 1) {
        int y = __shfl_up_sync(0xFFFFFFFFu, v, o);
        if ((t & 31) >= o) v += y;
    }
    if ((t & 31) == 31) wsum[t >> 5] = v;
    __syncthreads();
    if (t < 32) {
        int w = wsum[t];
        #pragma unroll
        for (int o = 1; o < 32; o <<= 1) {
            int y = __shfl_up_sync(0xFFFFFFFFu, w, o);
            if (t >= o) w += y;
        }
        wsum[t] = w;
    }
    __syncthreads();
    int base = (t >= 32) ? wsum[(t >> 5) - 1] : 0;
    int incl = v + base;
    if (i < n) rowptr[i] = incl - x;
    if (t == 1023) bsum[blockIdx.x] = incl;
}

// scanC: integrates the block-sum prefix in-kernel (no separate scanB launch).
__global__ __launch_bounds__(1024)
void scanC_kernel(int* __restrict__ rowptr, int* __restrict__ off,
                  const int* __restrict__ bsum, int n, int E)
{
    __shared__ int blockOff;
    int t = threadIdx.x;
    if (t < 32) {
        int acc = 0;
        for (int j = t; j < blockIdx.x; j += 32) acc += __ldg(&bsum[j]);
        #pragma unroll
        for (int o = 16; o; o >>= 1) acc += __shfl_down_sync(0xFFFFFFFFu, acc, o);
        if (t == 0) blockOff = acc;
    }
    __syncthreads();
    int i = blockIdx.x * 1024 + t;
    if (i < n) {
        int r = rowptr[i] + blockOff;
        rowptr[i] = r;
        off[i] = r;
    }
    if (i == 0) rowptr[n] = E;
}

__global__ __launch_bounds__(256)
void fill_kernel(const int* __restrict__ dest, const int* __restrict__ src,
                 int E, int* __restrict__ off, int* __restrict__ srcs)
{
    int i = blockIdx.x * blockDim.x + threadIdx.x;
    int stride = gridDim.x * blockDim.x;
    for (; i < E; i += stride) {
        int d = dest[i];
        int p = atomicAdd(&off[d], 1);
        srcs[p] = src[i];
    }
}

// ---------------------------------------------------------------------------
// Scalar segment-sums.
// ---------------------------------------------------------------------------
__global__ __launch_bounds__(256)
void scalar_agg_kernel(const float* __restrict__ src, float* __restrict__ dst,
                       const int* __restrict__ rowptr, const int* __restrict__ srcs,
                       int N)
{
    int d = blockIdx.x * 256 + threadIdx.x;
    if (d >= N) return;
    int b = __ldg(&rowptr[d]), e = __ldg(&rowptr[d + 1]);
    float s = 0.f;
    for (int i = b; i < e; i++) s += __ldg(&src[__ldg(&srcs[i])]);
    dst[d] = s;
}

__global__ __launch_bounds__(256)
void c1c2_kernel(const float* __restrict__ ev, const float* __restrict__ dv,
                 float* __restrict__ c1, float* __restrict__ c2,
                 const int* __restrict__ rowptr, const int* __restrict__ srcs,
                 int N)
{
    int d = blockIdx.x * 256 + threadIdx.x;
    if (d >= N) return;
    int b = __ldg(&rowptr[d]), e = __ldg(&rowptr[d + 1]);
    float s1 = 0.f, s2 = 0.f;
    for (int i = b; i < e; i++) {
        int s = __ldg(&srcs[i]);
        s1 += __ldg(&ev[s]);
        s2 += __ldg(&dv[s]);
    }
    c1[d] = s1;
    c2[d] = s2;
}

// ---------------------------------------------------------------------------
// CSR feature aggregations. One warp per dest row; fp32 accumulation.
// fp32 source variant (layer 1) and fp16 source variant (layers 2, 3).
// ---------------------------------------------------------------------------
__device__ __forceinline__ float4 csr_gather_row_f32(const float* __restrict__ src,
                                                     const int* __restrict__ srcs,
                                                     int beg, int end, int lane)
{
    float4 acc = make_float4(0.f, 0.f, 0.f, 0.f);
    int i = beg;
    for (; i + 4 <= end; i += 4) {
        int s0 = __ldg(&srcs[i + 0]);
        int s1 = __ldg(&srcs[i + 1]);
        int s2 = __ldg(&srcs[i + 2]);
        int s3 = __ldg(&srcs[i + 3]);
        float4 a = __ldg(reinterpret_cast<const float4*>(src + (size_t)s0 * D) + lane);
        float4 b = __ldg(reinterpret_cast<const float4*>(src + (size_t)s1 * D) + lane);
        float4 c = __ldg(reinterpret_cast<const float4*>(src + (size_t)s2 * D) + lane);
        float4 e = __ldg(reinterpret_cast<const float4*>(src + (size_t)s3 * D) + lane);
        acc.x += (a.x + b.x) + (c.x + e.x);
        acc.y += (a.y + b.y) + (c.y + e.y);
        acc.z += (a.z + b.z) + (c.z + e.z);
        acc.w += (a.w + b.w) + (c.w + e.w);
    }
    for (; i < end; i++) {
        int s0 = __ldg(&srcs[i]);
        float4 a = __ldg(reinterpret_cast<const float4*>(src + (size_t)s0 * D) + lane);
        acc.x += a.x; acc.y += a.y; acc.z += a.z; acc.w += a.w;
    }
    return acc;
}

__device__ __forceinline__ void acc_half4(float4& acc, uint2 p)
{
    float2 f01 = __half22float2(*reinterpret_cast<const __half2*>(&p.x));
    float2 f23 = __half22float2(*reinterpret_cast<const __half2*>(&p.y));
    acc.x += f01.x; acc.y += f01.y; acc.z += f23.x; acc.w += f23.y;
}

__device__ __forceinline__ float4 csr_gather_row_f16(const __half* __restrict__ src,
                                                     const int* __restrict__ srcs,
                                                     int beg, int end, int lane)
{
    float4 acc = make_float4(0.f, 0.f, 0.f, 0.f);
    int i = beg;
    for (; i + 4 <= end; i += 4) {
        int s0 = __ldg(&srcs[i + 0]);
        int s1 = __ldg(&srcs[i + 1]);
        int s2 = __ldg(&srcs[i + 2]);
        int s3 = __ldg(&srcs[i + 3]);
        uint2 a = __ldg(reinterpret_cast<const uint2*>(src + (size_t)s0 * D) + lane);
        uint2 b = __ldg(reinterpret_cast<const uint2*>(src + (size_t)s1 * D) + lane);
        uint2 c = __ldg(reinterpret_cast<const uint2*>(src + (size_t)s2 * D) + lane);
        uint2 e = __ldg(reinterpret_cast<const uint2*>(src + (size_t)s3 * D) + lane);
        acc_half4(acc, a); acc_half4(acc, b); acc_half4(acc, c); acc_half4(acc, e);
    }
    for (; i < end; i++) {
        int s0 = __ldg(&srcs[i]);
        uint2 a = __ldg(reinterpret_cast<const uint2*>(src + (size_t)s0 * D) + lane);
        acc_half4(acc, a);
    }
    return acc;
}

__device__ __forceinline__ uint2 pack_half4(float4 v)
{
    __half2 h01 = __float22half2_rn(make_float2(v.x, v.y));
    __half2 h23 = __float22half2_rn(make_float2(v.z, v.w));
    uint2 r;
    r.x = *reinterpret_cast<uint32_t*>(&h01);
    r.y = *reinterpret_cast<uint32_t*>(&h23);
    return r;
}

// agg1: fp32 source -> fp16 dest
__global__ __launch_bounds__(256)
void csr_agg_f32_to_f16_kernel(const float* __restrict__ src,
                               __half* __restrict__ dst,
                               const int* __restrict__ rowptr,
                               const int* __restrict__ srcs,
                               int N)
{
    int d = blockIdx.x * 8 + (threadIdx.x >> 5);
    if (d >= N) return;
    int lane = threadIdx.x & 31;
    float4 acc = csr_gather_row_f32(src, srcs, __ldg(&rowptr[d]), __ldg(&rowptr[d + 1]), lane);
    *(reinterpret_cast<uint2*>(dst + (size_t)d * D) + lane) = pack_half4(acc);
}

// agg2: fp16 source -> fp16 dest
__global__ __launch_bounds__(256)
void csr_agg_f16_to_f16_kernel(const __half* __restrict__ src,
                               __half* __restrict__ dst,
                               const int* __restrict__ rowptr,
                               const int* __restrict__ srcs,
                               int N)
{
    int d = blockIdx.x * 8 + (threadIdx.x >> 5);
    if (d >= N) return;
    int lane = threadIdx.x & 31;
    float4 acc = csr_gather_row_f16(src, srcs, __ldg(&rowptr[d]), __ldg(&rowptr[d + 1]), lane);
    *(reinterpret_cast<uint2*>(dst + (size_t)d * D) + lane) = pack_half4(acc);
}

// agg3: fp16 source -> bf16 split dest (GEMM A operand)
__global__ __launch_bounds__(256)
void csr_agg_f16_split_kernel(const __half* __restrict__ src,
                              __nv_bfloat16* __restrict__ dhi,
                              __nv_bfloat16* __restrict__ dlo,
                              const int* __restrict__ rowptr,
                              const int* __restrict__ srcs,
                              int N)
{
    int d = blockIdx.x * 8 + (threadIdx.x >> 5);
    if (d >= N) return;
    int lane = threadIdx.x & 31;
    float4 acc = csr_gather_row_f16(src, srcs, __ldg(&rowptr[d]), __ldg(&rowptr[d + 1]), lane);

    __nv_bfloat16 h0, l0, h1, l1, h2, l2, h3, l3;
    bf16_split(acc.x, h0, l0); bf16_split(acc.y, h1, l1);
    bf16_split(acc.z, h2, l2); bf16_split(acc.w, h3, l3);
    __nv_bfloat162 hi01 = __nv_bfloat162(h0, h1), hi23 = __nv_bfloat162(h2, h3);
    __nv_bfloat162 lo01 = __nv_bfloat162(l0, l1), lo23 = __nv_bfloat162(l2, l3);
    uint2 hv, lv;
    hv.x = *(uint32_t*)&hi01; hv.y = *(uint32_t*)&hi23;
    lv.x = *(uint32_t*)&lo01; lv.y = *(uint32_t*)&lo23;
    *(uint2*)(dhi + (size_t)d * D + lane * 4) = hv;
    *(uint2*)(dlo + (size_t)d * D + lane * 4) = lv;
}

// ---------------------------------------------------------------------------
extern "C" void kernel_launch(void* const* d_in, const int* in_sizes, int n_in,
                              void* d_out, int out_size)
{
    const float* X_v    = (const float*)d_in[1];
    const int*   edge_u = (const int*)  d_in[2];
    const int*   edge_v = (const int*)  d_in[3];
    const float* W0     = (const float*)d_in[4];
    const float* b0     = (const float*)d_in[5];
    const float* W1     = (const float*)d_in[6];
    const float* b1     = (const float*)d_in[7];
    const float* W2     = (const float*)d_in[8];
    const float* b2     = (const float*)d_in[9];
    float*       out    = (float*)d_out;

    const int N_V = in_sizes[1] / D;
    const int E   = in_sizes[2];
    const int N_U = out_size / D;

    float *P, *gg1, *gg2, *du, *dv, *ev, *c1, *c2;
    __half *bufY, *bufZ;
    __nv_bfloat16 *hi, *lo, *wthi, *wtlo;
    cudaGetSymbolAddress((void**)&bufY, g_bufY);
    cudaGetSymbolAddress((void**)&bufZ, g_bufZ);
    cudaGetSymbolAddress((void**)&hi,   g_hi);
    cudaGetSymbolAddress((void**)&lo,   g_lo);
    cudaGetSymbolAddress((void**)&P,    g_P);
    cudaGetSymbolAddress((void**)&wthi, g_wthi);
    cudaGetSymbolAddress((void**)&wtlo, g_wtlo);
    cudaGetSymbolAddress((void**)&gg1,  g_g1);
    cudaGetSymbolAddress((void**)&gg2,  g_g2);
    cudaGetSymbolAddress((void**)&du,   g_du);
    cudaGetSymbolAddress((void**)&dv,   g_dv);
    cudaGetSymbolAddress((void**)&ev,   g_ev);
    cudaGetSymbolAddress((void**)&c1,   g_c1);
    cudaGetSymbolAddress((void**)&c2,   g_c2);
    int *rowptr_u, *rowptr_v, *off_u, *off_v, *srcs_u, *srcs_v, *bsum_u, *bsum_v;
    cudaGetSymbolAddress((void**)&rowptr_u, g_rowptr_u);
    cudaGetSymbolAddress((void**)&rowptr_v, g_rowptr_v);
    cudaGetSymbolAddress((void**)&off_u, g_off_u);
    cudaGetSymbolAddress((void**)&off_v, g_off_v);
    cudaGetSymbolAddress((void**)&srcs_u, g_srcs_u);
    cudaGetSymbolAddress((void**)&srcs_v, g_srcs_v);
    cudaGetSymbolAddress((void**)&bsum_u, g_bsum_u);
    cudaGetSymbolAddress((void**)&bsum_v, g_bsum_v);

    cudaFuncSetAttribute(gemm_final_kernel,
                         cudaFuncAttributeMaxDynamicSharedMemorySize, SM_TOT);

    static cudaStream_t sV = nullptr, sW = nullptr;
    static cudaEvent_t eFork = nullptr, eU = nullptr, eBV = nullptr,
                       eSC = nullptr, eW = nullptr;
    if (sV == nullptr) {
        cudaStreamCreateWithFlags(&sV, cudaStreamNonBlocking);
        cudaStreamCreateWithFlags(&sW, cudaStreamNonBlocking);
        cudaEventCreateWithFlags(&eFork, cudaEventDisableTiming);
        cudaEventCreateWithFlags(&eU,    cudaEventDisableTiming);
        cudaEventCreateWithFlags(&eBV,   cudaEventDisableTiming);
        cudaEventCreateWithFlags(&eSC,   cudaEventDisableTiming);
        cudaEventCreateWithFlags(&eW,    cudaEventDisableTiming);
    }

    const int nb_u = (N_U + 1023) / 1024;
    const int nb_v = (N_V + 1023) / 1024;
    const int aggBlocksU = (N_U + 7) / 8;
    const int aggBlocksV = (N_V + 7) / 8;
    const int gemmBlocksU = (N_U + 63) / 64;

    // ---- fork ----
    cudaEventRecord(eFork, 0);
    cudaStreamWaitEvent(sV, eFork, 0);
    cudaStreamWaitEvent(sW, eFork, 0);

    // ---- main stream: build_u (v2u CSR) ----
    zero_int_kernel<<<(N_U + 255) / 256, 256, 0, 0>>>(off_u, N_U);
    hist_kernel<<<256, 256, 0, 0>>>(edge_u, E, off_u);
    scanA_kernel<<<nb_u, 1024, 0, 0>>>(off_u, rowptr_u, bsum_u, du, N_U);
    scanC_kernel<<<nb_u, 1024, 0, 0>>>(rowptr_u, off_u, bsum_u, N_U, E);
    fill_kernel<<<512, 256, 0, 0>>>(edge_u, edge_v, E, off_u, srcs_u);
    cudaEventRecord(eU, 0);

    // ---- stream V: build_v (u2v CSR) + scalar-degree chain ----
    zero_int_kernel<<<(N_V + 255) / 256, 256, 0, sV>>>(off_v, N_V);
    hist_kernel<<<256, 256, 0, sV>>>(edge_v, E, off_v);
    scanA_kernel<<<nb_v, 1024, 0, sV>>>(off_v, rowptr_v, bsum_v, dv, N_V);
    scanC_kernel<<<nb_v, 1024, 0, sV>>>(rowptr_v, off_v, bsum_v, N_V, E);
    fill_kernel<<<512, 256, 0, sV>>>(edge_v, edge_u, E, off_v, srcs_v);
    cudaEventRecord(eBV, sV);
    cudaStreamWaitEvent(sV, eU, 0);
    scalar_agg_kernel<<<(N_V + 255) / 256, 256, 0, sV>>>(du, ev, rowptr_v, srcs_v, N_V);
    c1c2_kernel<<<(N_U + 255) / 256, 256, 0, sV>>>(ev, dv, c1, c2, rowptr_u, srcs_u, N_U);
    cudaEventRecord(eSC, sV);

    // ---- stream W: weight chain ----
    small_gemm_kernel<<<129, 128, 0, sW>>>(W1, W2, b1, P, gg2);
    small_gemm_split_kernel<<<129, 128, 0, sW>>>(W0, P, b0, wthi, wtlo, gg1);
    cudaEventRecord(eW, sW);

    // ---- main stream: feature aggregation chain (fp16 intermediates) ----
    csr_agg_f32_to_f16_kernel<<<aggBlocksU, 256, 0, 0>>>(X_v, bufY, rowptr_u, srcs_u, N_U);
    cudaStreamWaitEvent(0, eBV, 0);
    csr_agg_f16_to_f16_kernel<<<aggBlocksV, 256, 0, 0>>>(bufY, bufZ, rowptr_v, srcs_v, N_V);
    csr_agg_f16_split_kernel<<<aggBlocksU, 256, 0, 0>>>(bufZ, hi, lo, rowptr_u, srcs_u, N_U);

    // ---- join + final GEMM ----
    cudaStreamWaitEvent(0, eSC, 0);
    cudaStreamWaitEvent(0, eW, 0);
    gemm_final_kernel<<<gemmBlocksU, 128, SM_TOT, 0>>>(hi, lo, wthi, wtlo,
                                                       gg1, gg2, b2, c1, c2, du,
                                                       out, N_U);
}

// round 11
// speedup vs baseline: 1.6221x; 1.0504x over previous
#include <cuda_runtime.h>
#include <cuda_bf16.h>
#include <cuda_fp16.h>
#include <cstdint>

#define D 128
#define MAXN 50176
#define MAXE 640000

typedef unsigned long long u64;

// ---------------------------------------------------------------------------
// Scratch (no cudaMalloc allowed).
// ---------------------------------------------------------------------------
__device__ __half g_Xh[(size_t)MAXN * D];    // fp16 copy of X_v
__device__ __half g_bufY[(size_t)MAXN * D];  // S_u = v2u(X_v)
__device__ __half g_bufZ[(size_t)MAXN * D];  // T_v = u2v(S_u)
__device__ __half g_A[(size_t)MAXN * D];     // R = v2u(T_v)  (GEMM A operand)
__device__ float  g_P[D * D];                // W1@W2
__device__ __half g_wthi[D * D];             // (W0@W1@W2)^T fp16 hi
__device__ __half g_wtlo[D * D];             // residual lo
__device__ float  g_g1[D];                   // b0@W1@W2
__device__ float  g_g2[D];                   // b1@W2
__device__ float  g_du[MAXN];
__device__ float  g_dv[MAXN];
__device__ float  g_ev[MAXN];
__device__ float  g_c1[MAXN];
__device__ float  g_c2[MAXN];

// CSR structures.
__device__ int g_rowptr_u[MAXN + 1];
__device__ int g_rowptr_v[MAXN + 1];
__device__ int g_off_u[MAXN];
__device__ int g_off_v[MAXN];
__device__ int g_srcs_u[MAXE];
__device__ int g_srcs_v[MAXE];
__device__ int g_bsum_u[64];
__device__ int g_bsum_v[64];

// ---------------------------------------------------------------------------
// mma.sync / ldmatrix helpers (baseline PTX, works on compute_103)
// ---------------------------------------------------------------------------
__device__ __forceinline__ uint32_t smem_u32(const void* p) {
    uint32_t a;
    asm("{ .reg .u64 t; cvta.to.shared.u64 t, %1; cvt.u32.u64 %0, t; }" : "=r"(a) : "l"(p));
    return a;
}

__device__ __forceinline__ void ldm_x4(uint32_t (&r)[4], uint32_t addr) {
    asm volatile("ldmatrix.sync.aligned.m8n8.x4.shared.b16 {%0,%1,%2,%3}, [%4];"
                 : "=r"(r[0]), "=r"(r[1]), "=r"(r[2]), "=r"(r[3]) : "r"(addr));
}

__device__ __forceinline__ void mma_f16(float (&c)[4], const uint32_t (&a)[4],
                                        uint32_t b0, uint32_t b1) {
    asm volatile(
        "mma.sync.aligned.m16n8k16.row.col.f32.f16.f16.f32 "
        "{%0,%1,%2,%3}, {%4,%5,%6,%7}, {%8,%9}, {%0,%1,%2,%3};"
        : "+f"(c[0]), "+f"(c[1]), "+f"(c[2]), "+f"(c[3])
        : "r"(a[0]), "r"(a[1]), "r"(a[2]), "r"(a[3]), "r"(b0), "r"(b1));
}

__device__ __forceinline__ void f16_split(float f, __half& h, __half& l) {
    h = __float2half_rn(f);
    l = __float2half_rn(f - __half2float(h));
}

// ---------------------------------------------------------------------------
// Final tensor GEMM: out[64-row tile] = A @ W012 + c1*g1 + c2*g2 + du*g3
// A fp16 (exact), B = fp16 hi + fp16 lo (2 passes), fp32 accum.
// ---------------------------------------------------------------------------
#define STR 136
#define SM_G1   0
#define SM_G2   512
#define SM_G3   1024
#define SM_A    1536
#define SM_BHI  (SM_A + 64 * 272)        // 18944
#define SM_BLO  (SM_BHI + 128 * 272)     // 53760
#define SM_TOT  (SM_BLO + 128 * 272)     // 88576
#define SM_EP   1536
#define EPSTR   132

__global__ __launch_bounds__(128, 2)
void gemm_final_kernel(const __half* __restrict__ A,
                       const __half* __restrict__ Bhi,
                       const __half* __restrict__ Blo,
                       const float* __restrict__ g1,
                       const float* __restrict__ g2,
                       const float* __restrict__ g3,
                       const float* __restrict__ c1,
                       const float* __restrict__ c2,
                       const float* __restrict__ du,
                       float* __restrict__ Y,
                       int N)
{
    extern __shared__ char smem[];
    const uint32_t sb = smem_u32(smem);
    const int tid  = threadIdx.x;
    const int lane = tid & 31;
    const int warp = tid >> 5;
    const int rowBase = blockIdx.x * 64;

    ((float*)(smem + SM_G1))[tid] = g1[tid];
    ((float*)(smem + SM_G2))[tid] = g2[tid];
    ((float*)(smem + SM_G3))[tid] = g3[tid];

    #pragma unroll 4
    for (int i = tid; i < 128 * 16; i += 128) {
        int n = i >> 4, c = i & 15;
        uint32_t so = (uint32_t)(n * 272 + c * 16);
        *(uint4*)(smem + SM_BHI + so) = *(const uint4*)(Bhi + (size_t)n * D + c * 8);
        *(uint4*)(smem + SM_BLO + so) = *(const uint4*)(Blo + (size_t)n * D + c * 8);
    }
    #pragma unroll 4
    for (int i = tid; i < 64 * 16; i += 128) {
        int r = i >> 4, c = i & 15;
        int row = rowBase + r;
        uint4 v = make_uint4(0, 0, 0, 0);
        if (row < N)
            v = *(const uint4*)(A + (size_t)row * D + c * 8);
        *(uint4*)(smem + SM_A + (uint32_t)(r * 272 + c * 16)) = v;
    }
    __syncthreads();

    float acc[16][4];
    #pragma unroll
    for (int t = 0; t < 16; t++) {
        acc[t][0] = 0.f; acc[t][1] = 0.f; acc[t][2] = 0.f; acc[t][3] = 0.f;
    }

    const int wr = warp * 16;
    const uint32_t aRowOff = (uint32_t)((wr + (lane & 15)) * STR + ((lane >> 4) << 3)) * 2;
    const int nOff  = (lane & 7) + ((lane >> 4) & 1) * 8;
    const int kHalf = ((lane >> 3) & 1) * 8;
    const uint32_t bRowOff = (uint32_t)(nOff * STR + kHalf) * 2;
    const uint32_t aBase = sb + SM_A + aRowOff;

    #pragma unroll 1
    for (int pass = 0; pass < 2; pass++) {
        uint32_t bBase = sb + ((pass == 1) ? SM_BLO : SM_BHI) + bRowOff;
        #pragma unroll 2
        for (int k0 = 0; k0 < 128; k0 += 16) {
            uint32_t a[4];
            ldm_x4(a, aBase + k0 * 2);
            #pragma unroll
            for (int j = 0; j < 8; j++) {
                uint32_t b[4];
                ldm_x4(b, bBase + (uint32_t)(j * 16 * STR + k0) * 2);
                mma_f16(acc[2 * j],     a, b[0], b[1]);
                mma_f16(acc[2 * j + 1], a, b[2], b[3]);
            }
        }
    }
    __syncthreads();

    {
        float* ep = (float*)(smem + SM_EP);
        const int r0 = wr + (lane >> 2);
        const int cq = 2 * (lane & 3);
        #pragma unroll
        for (int t = 0; t < 16; t++) {
            int col = t * 8 + cq;
            *(float2*)(ep + r0 * EPSTR + col)       = make_float2(acc[t][0], acc[t][1]);
            *(float2*)(ep + (r0 + 8) * EPSTR + col) = make_float2(acc[t][2], acc[t][3]);
        }
    }
    __syncthreads();
    {
        const float*  ep  = (const float*)(smem + SM_EP);
        const float4* g1v = (const float4*)(smem + SM_G1);
        const float4* g2v = (const float4*)(smem + SM_G2);
        const float4* g3v = (const float4*)(smem + SM_G3);
        #pragma unroll 4
        for (int i = tid; i < 64 * 32; i += 128) {
            int r = i >> 5, c4 = i & 31;
            int row = rowBase + r;
            if (row < N) {
                float s1 = __ldg(&c1[row]);
                float s2 = __ldg(&c2[row]);
                float s3 = __ldg(&du[row]);
                float4 v  = *(const float4*)(ep + r * EPSTR + c4 * 4);
                float4 a1 = g1v[c4], a2 = g2v[c4], a3 = g3v[c4];
                v.x += s1 * a1.x + s2 * a2.x + s3 * a3.x;
                v.y += s1 * a1.y + s2 * a2.y + s3 * a3.y;
                v.z += s1 * a1.z + s2 * a2.z + s3 * a3.z;
                v.w += s1 * a1.w + s2 * a2.w + s3 * a3.w;
                *(float4*)(Y + (size_t)row * D + c4 * 4) = v;
            }
        }
    }
}

// ---------------------------------------------------------------------------
// Small fp32 GEMMs for the weight chain.
// ---------------------------------------------------------------------------
__global__ __launch_bounds__(128)
void small_gemm_kernel(const float* __restrict__ A, const float* __restrict__ B,
                       const float* __restrict__ v, float* __restrict__ C,
                       float* __restrict__ vout)
{
    __shared__ float sA[128];
    int r = blockIdx.x;
    int j = threadIdx.x;
    const float* arow = (r < 128) ? (A + (size_t)r * D) : v;
    sA[j] = arow[j];
    __syncthreads();
    float s = 0.f;
    #pragma unroll 8
    for (int k = 0; k < 128; k++) s += sA[k] * B[k * D + j];
    if (r < 128) C[(size_t)r * D + j] = s;
    else vout[j] = s;
}

__global__ __launch_bounds__(128)
void small_gemm_split_kernel(const float* __restrict__ A, const float* __restrict__ B,
                             const float* __restrict__ v,
                             __half* __restrict__ wthi,
                             __half* __restrict__ wtlo,
                             float* __restrict__ vout)
{
    __shared__ float sA[128];
    int r = blockIdx.x;
    int j = threadIdx.x;
    const float* arow = (r < 128) ? (A + (size_t)r * D) : v;
    sA[j] = arow[j];
    __syncthreads();
    float s = 0.f;
    #pragma unroll 8
    for (int k = 0; k < 128; k++) s += sA[k] * B[k * D + j];
    if (r < 128) {
        __half h, l;
        f16_split(s, h, l);
        wthi[(size_t)j * D + r] = h;   // [n=j][k=r] layout for the B operand
        wtlo[(size_t)j * D + r] = l;
    } else {
        vout[j] = s;
    }
}

// X_v fp32 -> fp16 (sequential, fully coalesced).
__global__ __launch_bounds__(256)
void f32_to_f16_kernel(const float* __restrict__ x, __half* __restrict__ y, int n4)
{
    int i = blockIdx.x * blockDim.x + threadIdx.x;
    int stride = gridDim.x * blockDim.x;
    for (; i < n4; i += stride) {
        float4 v = __ldg(reinterpret_cast<const float4*>(x) + i);
        __half2 a = __float22half2_rn(make_float2(v.x, v.y));
        __half2 b = __float22half2_rn(make_float2(v.z, v.w));
        uint2 r;
        r.x = *reinterpret_cast<uint32_t*>(&a);
        r.y = *reinterpret_cast<uint32_t*>(&b);
        reinterpret_cast<uint2*>(y)[i] = r;
    }
}

// ---------------------------------------------------------------------------
// CSR build (counting sort by destination).
// ---------------------------------------------------------------------------
__global__ __launch_bounds__(256)
void zero_int_kernel(int* __restrict__ p, int n)
{
    int i = blockIdx.x * blockDim.x + threadIdx.x;
    int stride = gridDim.x * blockDim.x;
    for (; i < n; i += stride) p[i] = 0;
}

__global__ __launch_bounds__(256)
void hist_kernel(const int* __restrict__ dest, int E, int* __restrict__ cnt)
{
    int i = blockIdx.x * blockDim.x + threadIdx.x;
    int stride = gridDim.x * blockDim.x;
    for (; i < E; i += stride) atomicAdd(&cnt[dest[i]], 1);
}

__global__ __launch_bounds__(1024)
void scanA_kernel(const int* __restrict__ cnt, int* __restrict__ rowptr,
                  int* __restrict__ bsum, float* __restrict__ deg, int n)
{
    __shared__ int wsum[32];
    int t = threadIdx.x;
    int i = blockIdx.x * 1024 + t;
    int x = (i < n) ? cnt[i] : 0;
    if (i < n) deg[i] = (float)x;

    int v = x;
    #pragma unroll
    for (int o = 1; o < 32; o <<= 1) {
        int y = __shfl_up_sync(0xFFFFFFFFu, v, o);
        if ((t & 31) >= o) v += y;
    }
    if ((t & 31) == 31) wsum[t >> 5] = v;
    __syncthreads();
    if (t < 32) {
        int w = wsum[t];
        #pragma unroll
        for (int o = 1; o < 32; o <<= 1) {
            int y = __shfl_up_sync(0xFFFFFFFFu, w, o);
            if (t >= o) w += y;
        }
        wsum[t] = w;
    }
    __syncthreads();
    int base = (t >= 32) ? wsum[(t >> 5) - 1] : 0;
    int incl = v + base;
    if (i < n) rowptr[i] = incl - x;
    if (t == 1023) bsum[blockIdx.x] = incl;
}

__global__ __launch_bounds__(1024)
void scanC_kernel(int* __restrict__ rowptr, int* __restrict__ off,
                  const int* __restrict__ bsum, int n, int E)
{
    __shared__ int blockOff;
    int t = threadIdx.x;
    if (t < 32) {
        int acc = 0;
        for (int j = t; j < blockIdx.x; j += 32) acc += __ldg(&bsum[j]);
        #pragma unroll
        for (int o = 16; o; o >>= 1) acc += __shfl_down_sync(0xFFFFFFFFu, acc, o);
        if (t == 0) blockOff = acc;
    }
    __syncthreads();
    int i = blockIdx.x * 1024 + t;
    if (i < n) {
        int r = rowptr[i] + blockOff;
        rowptr[i] = r;
        off[i] = r;
    }
    if (i == 0) rowptr[n] = E;
}

__global__ __launch_bounds__(256)
void fill_kernel(const int* __restrict__ dest, const int* __restrict__ src,
                 int E, int* __restrict__ off, int* __restrict__ srcs)
{
    int i = blockIdx.x * blockDim.x + threadIdx.x;
    int stride = gridDim.x * blockDim.x;
    for (; i < E; i += stride) {
        int d = dest[i];
        int p = atomicAdd(&off[d], 1);
        srcs[p] = src[i];
    }
}

// ---------------------------------------------------------------------------
// Scalar segment-sums.
// ---------------------------------------------------------------------------
__global__ __launch_bounds__(256)
void scalar_agg_kernel(const float* __restrict__ src, float* __restrict__ dst,
                       const int* __restrict__ rowptr, const int* __restrict__ srcs,
                       int N)
{
    int d = blockIdx.x * 256 + threadIdx.x;
    if (d >= N) return;
    int b = __ldg(&rowptr[d]), e = __ldg(&rowptr[d + 1]);
    float s = 0.f;
    for (int i = b; i < e; i++) s += __ldg(&src[__ldg(&srcs[i])]);
    dst[d] = s;
}

__global__ __launch_bounds__(256)
void c1c2_kernel(const float* __restrict__ ev, const float* __restrict__ dv,
                 float* __restrict__ c1, float* __restrict__ c2,
                 const int* __restrict__ rowptr, const int* __restrict__ srcs,
                 int N)
{
    int d = blockIdx.x * 256 + threadIdx.x;
    if (d >= N) return;
    int b = __ldg(&rowptr[d]), e = __ldg(&rowptr[d + 1]);
    float s1 = 0.f, s2 = 0.f;
    for (int i = b; i < e; i++) {
        int s = __ldg(&srcs[i]);
        s1 += __ldg(&ev[s]);
        s2 += __ldg(&dv[s]);
    }
    c1[d] = s1;
    c2[d] = s2;
}

// ---------------------------------------------------------------------------
// Dual-half-warp fp16 CSR aggregation.
// 16 lanes x uint4 (16B) cover a 256B fp16 row; the two half-warps process
// interleaved edge streams, combined with shfl_xor(16). 16 LDG/edge vs 32.
// ---------------------------------------------------------------------------
__device__ __forceinline__ void acc8(float (&acc)[8], uint4 p)
{
    float2 f;
    f = __half22float2(*reinterpret_cast<const __half2*>(&p.x)); acc[0] += f.x; acc[1] += f.y;
    f = __half22float2(*reinterpret_cast<const __half2*>(&p.y)); acc[2] += f.x; acc[3] += f.y;
    f = __half22float2(*reinterpret_cast<const __half2*>(&p.z)); acc[4] += f.x; acc[5] += f.y;
    f = __half22float2(*reinterpret_cast<const __half2*>(&p.w)); acc[6] += f.x; acc[7] += f.y;
}

__device__ __forceinline__ void csr_gather_dual(const __half* __restrict__ src,
                                                const int* __restrict__ srcs,
                                                int beg, int end, int l16, int half,
                                                float (&acc)[8])
{
    int i = beg + half;
    for (; i + 6 < end; i += 8) {
        int s0 = __ldg(&srcs[i]);
        int s1 = __ldg(&srcs[i + 2]);
        int s2 = __ldg(&srcs[i + 4]);
        int s3 = __ldg(&srcs[i + 6]);
        uint4 a = __ldg(reinterpret_cast<const uint4*>(src + (size_t)s0 * D) + l16);
        uint4 b = __ldg(reinterpret_cast<const uint4*>(src + (size_t)s1 * D) + l16);
        uint4 c = __ldg(reinterpret_cast<const uint4*>(src + (size_t)s2 * D) + l16);
        uint4 e = __ldg(reinterpret_cast<const uint4*>(src + (size_t)s3 * D) + l16);
        acc8(acc, a); acc8(acc, b); acc8(acc, c); acc8(acc, e);
    }
    for (; i < end; i += 2) {
        int s0 = __ldg(&srcs[i]);
        uint4 a = __ldg(reinterpret_cast<const uint4*>(src + (size_t)s0 * D) + l16);
        acc8(acc, a);
    }
    #pragma unroll
    for (int k = 0; k < 8; k++)
        acc[k] += __shfl_xor_sync(0xFFFFFFFFu, acc[k], 16);
}

__device__ __forceinline__ uint4 pack_half8(const float (&acc)[8])
{
    uint4 r;
    __half2 h;
    h = __float22half2_rn(make_float2(acc[0], acc[1])); r.x = *reinterpret_cast<uint32_t*>(&h);
    h = __float22half2_rn(make_float2(acc[2], acc[3])); r.y = *reinterpret_cast<uint32_t*>(&h);
    h = __float22half2_rn(make_float2(acc[4], acc[5])); r.z = *reinterpret_cast<uint32_t*>(&h);
    h = __float22half2_rn(make_float2(acc[6], acc[7])); r.w = *reinterpret_cast<uint32_t*>(&h);
    return r;
}

__global__ __launch_bounds__(256)
void csr_agg_f16_kernel(const __half* __restrict__ src,
                        __half* __restrict__ dst,
                        const int* __restrict__ rowptr,
                        const int* __restrict__ srcs,
                        int N)
{
    int d = blockIdx.x * 8 + (threadIdx.x >> 5);
    if (d >= N) return;
    int lane = threadIdx.x & 31;
    int l16 = lane & 15, half = lane >> 4;
    float acc[8] = {0.f, 0.f, 0.f, 0.f, 0.f, 0.f, 0.f, 0.f};
    csr_gather_dual(src, srcs, __ldg(&rowptr[d]), __ldg(&rowptr[d + 1]), l16, half, acc);
    if (half == 0)
        reinterpret_cast<uint4*>(dst + (size_t)d * D)[l16] = pack_half8(acc);
}

// ---------------------------------------------------------------------------
extern "C" void kernel_launch(void* const* d_in, const int* in_sizes, int n_in,
                              void* d_out, int out_size)
{
    const float* X_v    = (const float*)d_in[1];
    const int*   edge_u = (const int*)  d_in[2];
    const int*   edge_v = (const int*)  d_in[3];
    const float* W0     = (const float*)d_in[4];
    const float* b0     = (const float*)d_in[5];
    const float* W1     = (const float*)d_in[6];
    const float* b1     = (const float*)d_in[7];
    const float* W2     = (const float*)d_in[8];
    const float* b2     = (const float*)d_in[9];
    float*       out    = (float*)d_out;

    const int N_V = in_sizes[1] / D;
    const int E   = in_sizes[2];
    const int N_U = out_size / D;

    float *P, *gg1, *gg2, *du, *dv, *ev, *c1, *c2;
    __half *Xh, *bufY, *bufZ, *Ah, *wthi, *wtlo;
    cudaGetSymbolAddress((void**)&Xh,   g_Xh);
    cudaGetSymbolAddress((void**)&bufY, g_bufY);
    cudaGetSymbolAddress((void**)&bufZ, g_bufZ);
    cudaGetSymbolAddress((void**)&Ah,   g_A);
    cudaGetSymbolAddress((void**)&P,    g_P);
    cudaGetSymbolAddress((void**)&wthi, g_wthi);
    cudaGetSymbolAddress((void**)&wtlo, g_wtlo);
    cudaGetSymbolAddress((void**)&gg1,  g_g1);
    cudaGetSymbolAddress((void**)&gg2,  g_g2);
    cudaGetSymbolAddress((void**)&du,   g_du);
    cudaGetSymbolAddress((void**)&dv,   g_dv);
    cudaGetSymbolAddress((void**)&ev,   g_ev);
    cudaGetSymbolAddress((void**)&c1,   g_c1);
    cudaGetSymbolAddress((void**)&c2,   g_c2);
    int *rowptr_u, *rowptr_v, *off_u, *off_v, *srcs_u, *srcs_v, *bsum_u, *bsum_v;
    cudaGetSymbolAddress((void**)&rowptr_u, g_rowptr_u);
    cudaGetSymbolAddress((void**)&rowptr_v, g_rowptr_v);
    cudaGetSymbolAddress((void**)&off_u, g_off_u);
    cudaGetSymbolAddress((void**)&off_v, g_off_v);
    cudaGetSymbolAddress((void**)&srcs_u, g_srcs_u);
    cudaGetSymbolAddress((void**)&srcs_v, g_srcs_v);
    cudaGetSymbolAddress((void**)&bsum_u, g_bsum_u);
    cudaGetSymbolAddress((void**)&bsum_v, g_bsum_v);

    cudaFuncSetAttribute(gemm_final_kernel,
                         cudaFuncAttributeMaxDynamicSharedMemorySize, SM_TOT);

    static cudaStream_t sV = nullptr, sW = nullptr;
    static cudaEvent_t eFork = nullptr, eU = nullptr, eBV = nullptr,
                       eSC = nullptr, eW = nullptr, eX = nullptr;
    if (sV == nullptr) {
        cudaStreamCreateWithFlags(&sV, cudaStreamNonBlocking);
        cudaStreamCreateWithFlags(&sW, cudaStreamNonBlocking);
        cudaEventCreateWithFlags(&eFork, cudaEventDisableTiming);
        cudaEventCreateWithFlags(&eU,    cudaEventDisableTiming);
        cudaEventCreateWithFlags(&eBV,   cudaEventDisableTiming);
        cudaEventCreateWithFlags(&eSC,   cudaEventDisableTiming);
        cudaEventCreateWithFlags(&eW,    cudaEventDisableTiming);
        cudaEventCreateWithFlags(&eX,    cudaEventDisableTiming);
    }

    const int nb_u = (N_U + 1023) / 1024;
    const int nb_v = (N_V + 1023) / 1024;
    const int aggBlocksU = (N_U + 7) / 8;
    const int aggBlocksV = (N_V + 7) / 8;
    const int gemmBlocksU = (N_U + 63) / 64;

    // ---- fork ----
    cudaEventRecord(eFork, 0);
    cudaStreamWaitEvent(sV, eFork, 0);
    cudaStreamWaitEvent(sW, eFork, 0);

    // ---- main stream: build_u (v2u CSR) ----
    zero_int_kernel<<<(N_U + 255) / 256, 256, 0, 0>>>(off_u, N_U);
    hist_kernel<<<256, 256, 0, 0>>>(edge_u, E, off_u);
    scanA_kernel<<<nb_u, 1024, 0, 0>>>(off_u, rowptr_u, bsum_u, du, N_U);
    scanC_kernel<<<nb_u, 1024, 0, 0>>>(rowptr_u, off_u, bsum_u, N_U, E);
    fill_kernel<<<512, 256, 0, 0>>>(edge_u, edge_v, E, off_u, srcs_u);
    cudaEventRecord(eU, 0);

    // ---- stream V: build_v (u2v CSR) + scalar-degree chain ----
    zero_int_kernel<<<(N_V + 255) / 256, 256, 0, sV>>>(off_v, N_V);
    hist_kernel<<<256, 256, 0, sV>>>(edge_v, E, off_v);
    scanA_kernel<<<nb_v, 1024, 0, sV>>>(off_v, rowptr_v, bsum_v, dv, N_V);
    scanC_kernel<<<nb_v, 1024, 0, sV>>>(rowptr_v, off_v, bsum_v, N_V, E);
    fill_kernel<<<512, 256, 0, sV>>>(edge_v, edge_u, E, off_v, srcs_v);
    cudaEventRecord(eBV, sV);
    cudaStreamWaitEvent(sV, eU, 0);
    scalar_agg_kernel<<<(N_V + 255) / 256, 256, 0, sV>>>(du, ev, rowptr_v, srcs_v, N_V);
    c1c2_kernel<<<(N_U + 255) / 256, 256, 0, sV>>>(ev, dv, c1, c2, rowptr_u, srcs_u, N_U);
    cudaEventRecord(eSC, sV);

    // ---- stream W: X_v conversion + weight chain ----
    f32_to_f16_kernel<<<592, 256, 0, sW>>>(X_v, Xh, N_V * (D / 4));
    cudaEventRecord(eX, sW);
    small_gemm_kernel<<<129, 128, 0, sW>>>(W1, W2, b1, P, gg2);
    small_gemm_split_kernel<<<129, 128, 0, sW>>>(W0, P, b0, wthi, wtlo, gg1);
    cudaEventRecord(eW, sW);

    // ---- main stream: feature aggregation chain (fp16, dual-half gather) ----
    cudaStreamWaitEvent(0, eX, 0);
    csr_agg_f16_kernel<<<aggBlocksU, 256, 0, 0>>>(Xh, bufY, rowptr_u, srcs_u, N_U);
    cudaStreamWaitEvent(0, eBV, 0);
    csr_agg_f16_kernel<<<aggBlocksV, 256, 0, 0>>>(bufY, bufZ, rowptr_v, srcs_v, N_V);
    csr_agg_f16_kernel<<<aggBlocksU, 256, 0, 0>>>(bufZ, Ah, rowptr_u, srcs_u, N_U);

    // ---- join + final GEMM ----
    cudaStreamWaitEvent(0, eSC, 0);
    cudaStreamWaitEvent(0, eW, 0);
    gemm_final_kernel<<<gemmBlocksU, 128, SM_TOT, 0>>>(Ah, wthi, wtlo,
                                                       gg1, gg2, b2, c1, c2, du,
                                                       out, N_U);
}